// round 1
// baseline (speedup 1.0000x reference)
#include <cuda_runtime.h>

// Problem constants
#define Bb 2
#define Sq 2048
#define Ee 1024
#define Hh 16
#define Dd 64
#define Mrows (Bb*Sq)   // 4096

// Scratch (device globals: allocation-free, graph-capturable)
__device__ float g_q[(size_t)Bb*Hh*Sq*Dd];
__device__ float g_k[(size_t)Bb*Hh*Sq*Dd];
__device__ float g_v[(size_t)Bb*Hh*Sq*Dd];
__device__ float g_o[(size_t)Bb*Sq*Ee];

// ---------------------------------------------------------------------------
// SGEMM: C[M,N] = A[M,K] @ Bw[N,K]^T + bias[N]
// 128x128 block, BK=16, 256 threads, 8x8 per thread (4+4 split), float4 I/O.
// SCATTER=1: epilogue scatters into per-head Q/K/V [B,H,S,D] buffers.
// ---------------------------------------------------------------------------
template<int SCATTER>
__global__ __launch_bounds__(256)
void sgemm_kernel(const float* __restrict__ A, const float* __restrict__ Bw,
                  const float* __restrict__ bias, float* __restrict__ C,
                  float* __restrict__ Cq, float* __restrict__ Ck,
                  float* __restrict__ Cv, int M, int N, int K)
{
    const int BK = 16;
    __shared__ float As[BK][132];   // 132: keeps 16B alignment, avoids bank conflicts
    __shared__ float Bs[BK][132];

    int tid = threadIdx.x;
    int m0 = blockIdx.y * 128;
    int n0 = blockIdx.x * 128;
    int arow = tid >> 2;            // 0..63
    int acol = (tid & 3) << 2;      // 0,4,8,12
    int tx = tid & 15;
    int ty = tid >> 4;

    float acc[8][8];
    #pragma unroll
    for (int i = 0; i < 8; i++)
        #pragma unroll
        for (int j = 0; j < 8; j++) acc[i][j] = 0.f;

    const float* Ap = A + (size_t)m0 * K;
    const float* Bp = Bw + (size_t)n0 * K;

    for (int kt = 0; kt < K; kt += BK) {
        #pragma unroll
        for (int hh = 0; hh < 2; hh++) {
            int r = arow + hh * 64;
            float4 va = *(const float4*)(Ap + (size_t)r * K + kt + acol);
            As[acol+0][r] = va.x; As[acol+1][r] = va.y;
            As[acol+2][r] = va.z; As[acol+3][r] = va.w;
            float4 vb = *(const float4*)(Bp + (size_t)r * K + kt + acol);
            Bs[acol+0][r] = vb.x; Bs[acol+1][r] = vb.y;
            Bs[acol+2][r] = vb.z; Bs[acol+3][r] = vb.w;
        }
        __syncthreads();
        #pragma unroll
        for (int k = 0; k < BK; k++) {
            float ra[8], rb[8];
            *(float4*)(ra)     = *(const float4*)(&As[k][ty*4]);
            *(float4*)(ra + 4) = *(const float4*)(&As[k][64 + ty*4]);
            *(float4*)(rb)     = *(const float4*)(&Bs[k][tx*4]);
            *(float4*)(rb + 4) = *(const float4*)(&Bs[k][64 + tx*4]);
            #pragma unroll
            for (int i = 0; i < 8; i++)
                #pragma unroll
                for (int j = 0; j < 8; j++)
                    acc[i][j] = fmaf(ra[i], rb[j], acc[i][j]);
        }
        __syncthreads();
    }

    #pragma unroll
    for (int i = 0; i < 8; i++) {
        int ri = (i < 4) ? (ty*4 + i) : (64 + ty*4 + i - 4);
        int m = m0 + ri;
        #pragma unroll
        for (int j = 0; j < 8; j++) {
            int cj = (j < 4) ? (tx*4 + j) : (64 + tx*4 + j - 4);
            int n = n0 + cj;
            float v = acc[i][j] + bias[n];
            if (SCATTER == 0) {
                C[(size_t)m * N + n] = v;
            } else {
                int part = n >> 10;          // 0=q,1=k,2=v
                int e = n & 1023;
                int hh = e >> 6;
                int d  = e & 63;
                int b  = m >> 11;            // S = 2048
                int s  = m & 2047;
                size_t idx = (((size_t)(b * Hh + hh)) * Sq + s) * Dd + d;
                float* dst = (part == 0) ? Cq : (part == 1 ? Ck : Cv);
                dst[idx] = v;
            }
        }
    }
}

// ---------------------------------------------------------------------------
// Causal flash attention, fp32. One block = (b,h, 128 q-rows); one thread =
// one q row (q + o accumulator in registers). K/V tiles of 64 in smem.
// Online softmax with deferred rescale every 16 keys.
// ---------------------------------------------------------------------------
__global__ __launch_bounds__(128)
void attn_kernel(const float* __restrict__ Q, const float* __restrict__ K,
                 const float* __restrict__ V, float* __restrict__ O)
{
    const float SCALE = 0.125f;   // 64^-0.5
    __shared__ float Ks[64][Dd];
    __shared__ float Vs[64][Dd];

    int bh  = blockIdx.y;         // b*16 + h
    int qt  = blockIdx.x;
    int tid = threadIdx.x;
    int qg  = qt * 128 + tid;
    int b   = bh >> 4, hh = bh & 15;

    const float* Qp = Q + ((size_t)bh * Sq + qg) * Dd;
    float q[Dd];
    #pragma unroll
    for (int d = 0; d < Dd; d += 4)
        *(float4*)(q + d) = *(const float4*)(Qp + d);

    float m = -1e30f, l = 0.f;
    float o[Dd];
    #pragma unroll
    for (int d = 0; d < Dd; d++) o[d] = 0.f;

    const float* Kp = K + (size_t)bh * Sq * Dd;
    const float* Vp = V + (size_t)bh * Sq * Dd;
    int kend = qt * 128 + 128;

    for (int kt0 = 0; kt0 < kend; kt0 += 64) {
        __syncthreads();
        #pragma unroll
        for (int t = 0; t < 8; t++) {
            int vec = t * 128 + tid;
            int row = vec >> 4;
            int col = (vec & 15) << 2;
            *(float4*)(&Ks[row][col]) =
                *(const float4*)(Kp + (size_t)(kt0 + row) * Dd + col);
            *(float4*)(&Vs[row][col]) =
                *(const float4*)(Vp + (size_t)(kt0 + row) * Dd + col);
        }
        __syncthreads();

        for (int c = 0; c < 64; c += 16) {
            if (kt0 + c > qg) break;          // whole chunk masked -> done with tile
            float s[16];
            #pragma unroll
            for (int j = 0; j < 16; j++) {
                float acc = 0.f;
                #pragma unroll
                for (int d = 0; d < Dd; d += 4) {
                    float4 kv = *(const float4*)(&Ks[c + j][d]);
                    acc = fmaf(q[d+0], kv.x, acc);
                    acc = fmaf(q[d+1], kv.y, acc);
                    acc = fmaf(q[d+2], kv.z, acc);
                    acc = fmaf(q[d+3], kv.w, acc);
                }
                s[j] = (kt0 + c + j <= qg) ? acc * SCALE : -1e30f;
            }
            float mt = m;
            #pragma unroll
            for (int j = 0; j < 16; j++) mt = fmaxf(mt, s[j]);
            float alpha = __expf(m - mt);     // m=-1e30 first time -> alpha=0
            m = mt;
            l *= alpha;
            #pragma unroll
            for (int d = 0; d < Dd; d++) o[d] *= alpha;
            #pragma unroll
            for (int j = 0; j < 16; j++) {
                float p = __expf(s[j] - mt);  // masked keys underflow to 0
                l += p;
                #pragma unroll
                for (int d = 0; d < Dd; d += 4) {
                    float4 vv = *(const float4*)(&Vs[c + j][d]);
                    o[d+0] = fmaf(p, vv.x, o[d+0]);
                    o[d+1] = fmaf(p, vv.y, o[d+1]);
                    o[d+2] = fmaf(p, vv.z, o[d+2]);
                    o[d+3] = fmaf(p, vv.w, o[d+3]);
                }
            }
        }
    }

    float inv = 1.f / l;
    float* Op = O + ((size_t)b * Sq + qg) * Ee + hh * Dd;   // merged-head layout
    #pragma unroll
    for (int d = 0; d < Dd; d += 4) {
        float4 vv = make_float4(o[d]*inv, o[d+1]*inv, o[d+2]*inv, o[d+3]*inv);
        *(float4*)(Op + d) = vv;
    }
}

// ---------------------------------------------------------------------------
extern "C" void kernel_launch(void* const* d_in, const int* in_sizes, int n_in,
                              void* d_out, int out_size)
{
    const float* x      = (const float*)d_in[0];
    const float* W_attn = (const float*)d_in[1];
    const float* b_attn = (const float*)d_in[2];
    const float* W_proj = (const float*)d_in[3];
    const float* b_proj = (const float*)d_in[4];
    // d_in[5] = causal tril mask (int32) -- causality applied analytically
    float* out = (float*)d_out;

    float *qp, *kp, *vp, *op;
    cudaGetSymbolAddress((void**)&qp, g_q);
    cudaGetSymbolAddress((void**)&kp, g_k);
    cudaGetSymbolAddress((void**)&vp, g_v);
    cudaGetSymbolAddress((void**)&op, g_o);

    // 1) Fused QKV projection, scatter into [B,H,S,D] q/k/v
    dim3 g1((3 * Ee) / 128, Mrows / 128);
    sgemm_kernel<1><<<g1, 256>>>(x, W_attn, b_attn, nullptr,
                                 qp, kp, vp, Mrows, 3 * Ee, Ee);

    // 2) Causal attention -> merged heads [B,S,E]
    attn_kernel<<<dim3(Sq / 128, Bb * Hh), 128>>>(qp, kp, vp, op);

    // 3) Output projection
    dim3 g2(Ee / 128, Mrows / 128);
    sgemm_kernel<0><<<g2, 256>>>(op, W_proj, b_proj, out,
                                 nullptr, nullptr, nullptr, Mrows, Ee, Ee);
}

// round 2
// speedup vs baseline: 1.4174x; 1.4174x over previous
#include <cuda_runtime.h>

// Problem constants
#define Bb 2
#define Sq 2048
#define Ee 1024
#define Hh 16
#define Dd 64
#define Mrows (Bb*Sq)   // 4096

// Scratch (device globals: allocation-free, graph-capturable)
__device__ float g_q[(size_t)Bb*Hh*Sq*Dd];
__device__ float g_k[(size_t)Bb*Hh*Sq*Dd];
__device__ float g_v[(size_t)Bb*Hh*Sq*Dd];
__device__ float g_o[(size_t)Bb*Sq*Ee];

// ---------------------------------------------------------------------------
// SGEMM: C[M,N] = A[M,K] @ Bw[N,K]^T + bias[N]
// 128x128 block, BK=16, 256 threads, 8x8 per thread, double-buffered smem.
// SCATTER=1: epilogue scatters into per-head Q/K/V [B,H,S,D] buffers.
// ---------------------------------------------------------------------------
template<int SCATTER>
__global__ __launch_bounds__(256)
void sgemm_kernel(const float* __restrict__ A, const float* __restrict__ Bw,
                  const float* __restrict__ bias, float* __restrict__ C,
                  float* __restrict__ Cq, float* __restrict__ Ck,
                  float* __restrict__ Cv, int M, int N, int K)
{
    const int BK = 16;
    __shared__ float As[2][BK][132];
    __shared__ float Bs[2][BK][132];

    int tid = threadIdx.x;
    int m0 = blockIdx.y * 128;
    int n0 = blockIdx.x * 128;
    int arow = tid >> 2;            // 0..63
    int acol = (tid & 3) << 2;      // 0,4,8,12
    int tx = tid & 15;
    int ty = tid >> 4;

    float acc[8][8];
    #pragma unroll
    for (int i = 0; i < 8; i++)
        #pragma unroll
        for (int j = 0; j < 8; j++) acc[i][j] = 0.f;

    const float* Ap = A + (size_t)m0 * K;
    const float* Bp = Bw + (size_t)n0 * K;

    float4 pa[2], pb[2];
    // prologue: load kt=0
    #pragma unroll
    for (int hh = 0; hh < 2; hh++) {
        int r = arow + hh * 64;
        pa[hh] = *(const float4*)(Ap + (size_t)r * K + acol);
        pb[hh] = *(const float4*)(Bp + (size_t)r * K + acol);
    }
    #pragma unroll
    for (int hh = 0; hh < 2; hh++) {
        int r = arow + hh * 64;
        As[0][acol+0][r] = pa[hh].x; As[0][acol+1][r] = pa[hh].y;
        As[0][acol+2][r] = pa[hh].z; As[0][acol+3][r] = pa[hh].w;
        Bs[0][acol+0][r] = pb[hh].x; Bs[0][acol+1][r] = pb[hh].y;
        Bs[0][acol+2][r] = pb[hh].z; Bs[0][acol+3][r] = pb[hh].w;
    }
    __syncthreads();

    for (int kt = 0; kt < K; kt += BK) {
        int cur = (kt >> 4) & 1;
        bool more = (kt + BK) < K;
        if (more) {
            #pragma unroll
            for (int hh = 0; hh < 2; hh++) {
                int r = arow + hh * 64;
                pa[hh] = *(const float4*)(Ap + (size_t)r * K + kt + BK + acol);
                pb[hh] = *(const float4*)(Bp + (size_t)r * K + kt + BK + acol);
            }
        }
        #pragma unroll
        for (int k = 0; k < BK; k++) {
            float ra[8], rb[8];
            *(float4*)(ra)     = *(const float4*)(&As[cur][k][ty*4]);
            *(float4*)(ra + 4) = *(const float4*)(&As[cur][k][64 + ty*4]);
            *(float4*)(rb)     = *(const float4*)(&Bs[cur][k][tx*4]);
            *(float4*)(rb + 4) = *(const float4*)(&Bs[cur][k][64 + tx*4]);
            #pragma unroll
            for (int i = 0; i < 8; i++)
                #pragma unroll
                for (int j = 0; j < 8; j++)
                    acc[i][j] = fmaf(ra[i], rb[j], acc[i][j]);
        }
        if (more) {
            int nxt = cur ^ 1;
            #pragma unroll
            for (int hh = 0; hh < 2; hh++) {
                int r = arow + hh * 64;
                As[nxt][acol+0][r] = pa[hh].x; As[nxt][acol+1][r] = pa[hh].y;
                As[nxt][acol+2][r] = pa[hh].z; As[nxt][acol+3][r] = pa[hh].w;
                Bs[nxt][acol+0][r] = pb[hh].x; Bs[nxt][acol+1][r] = pb[hh].y;
                Bs[nxt][acol+2][r] = pb[hh].z; Bs[nxt][acol+3][r] = pb[hh].w;
            }
        }
        __syncthreads();
    }

    #pragma unroll
    for (int i = 0; i < 8; i++) {
        int ri = (i < 4) ? (ty*4 + i) : (64 + ty*4 + i - 4);
        int m = m0 + ri;
        #pragma unroll
        for (int j = 0; j < 8; j++) {
            int cj = (j < 4) ? (tx*4 + j) : (64 + tx*4 + j - 4);
            int n = n0 + cj;
            float v = acc[i][j] + bias[n];
            if (SCATTER == 0) {
                C[(size_t)m * N + n] = v;
            } else {
                int part = n >> 10;          // 0=q,1=k,2=v
                int e = n & 1023;
                int hh = e >> 6;
                int d  = e & 63;
                int b  = m >> 11;            // S = 2048
                int s  = m & 2047;
                size_t idx = (((size_t)(b * Hh + hh)) * Sq + s) * Dd + d;
                float* dst = (part == 0) ? Cq : (part == 1 ? Ck : Cv);
                dst[idx] = v;
            }
        }
    }
}

// ---------------------------------------------------------------------------
// Register-tiled causal flash attention (fp32).
// Block = (b,h, 128 q rows). K-tiles of 128. 256 threads, 8x8 scores/thread.
// P staged via smem in [k][q] layout (broadcast reads in PV phase).
// ---------------------------------------------------------------------------
#define QS_OFF  0
#define KT_OFF  (64*132)
#define VS_OFF  (KT_OFF + 64*132)
#define PS_OFF  (VS_OFF + 128*64)
#define ATTN_SMEM ((PS_OFF + 128*132) * 4)

__global__ __launch_bounds__(256)
void attn_kernel(const float* __restrict__ Q, const float* __restrict__ K,
                 const float* __restrict__ V, float* __restrict__ O)
{
    const float SCALE = 0.125f;   // 64^-0.5
    extern __shared__ float sm[];
    float* Qs  = sm + QS_OFF;     // [64][132]  d-major, pre-scaled
    float* Kts = sm + KT_OFF;     // [64][132]  d-major
    float* Vs  = sm + VS_OFF;     // [128][64]  k-major
    float* Ps  = sm + PS_OFF;     // [128][132] k-major

    int tid = threadIdx.x;
    int tx = tid & 15;
    int ty = tid >> 4;
    int bh = blockIdx.y;          // b*16 + h
    int qt = gridDim.x - 1 - (int)blockIdx.x;   // heavy tiles first
    int q0 = qt * 128;
    int b = bh >> 4, hh = bh & 15;

    // load + scale + transpose Q tile: Qs[d][q]
    const float* Qp = Q + ((size_t)bh * Sq + q0) * Dd;
    for (int i = tid; i < 128 * 16; i += 256) {
        int row = i >> 4;
        int cv  = (i & 15) << 2;
        float4 v = *(const float4*)(Qp + (size_t)row * Dd + cv);
        Qs[(cv+0)*132 + row] = v.x * SCALE;
        Qs[(cv+1)*132 + row] = v.y * SCALE;
        Qs[(cv+2)*132 + row] = v.z * SCALE;
        Qs[(cv+3)*132 + row] = v.w * SCALE;
    }

    float o[8][4];
    #pragma unroll
    for (int i = 0; i < 8; i++)
        #pragma unroll
        for (int j = 0; j < 4; j++) o[i][j] = 0.f;
    float mrow[8], lrow[8];
    #pragma unroll
    for (int i = 0; i < 8; i++) { mrow[i] = -1e30f; lrow[i] = 0.f; }

    const float* Kp = K + (size_t)bh * Sq * Dd;
    const float* Vp = V + (size_t)bh * Sq * Dd;

    for (int t = 0; t <= qt; t++) {
        int k0 = t * 128;
        __syncthreads();   // previous PV done before overwriting K/V tiles
        for (int i = tid; i < 128 * 16; i += 256) {
            int row = i >> 4;
            int cv  = (i & 15) << 2;
            float4 kv = *(const float4*)(Kp + (size_t)(k0 + row) * Dd + cv);
            Kts[(cv+0)*132 + row] = kv.x;
            Kts[(cv+1)*132 + row] = kv.y;
            Kts[(cv+2)*132 + row] = kv.z;
            Kts[(cv+3)*132 + row] = kv.w;
            float4 vv = *(const float4*)(Vp + (size_t)(k0 + row) * Dd + cv);
            *(float4*)(&Vs[row*64 + cv]) = vv;
        }
        __syncthreads();

        // score tile: s[8][8]
        float s[8][8];
        #pragma unroll
        for (int i = 0; i < 8; i++)
            #pragma unroll
            for (int j = 0; j < 8; j++) s[i][j] = 0.f;
        #pragma unroll 8
        for (int d = 0; d < 64; d++) {
            float ra[8], rb[8];
            *(float4*)(ra)     = *(const float4*)(&Qs[d*132 + ty*4]);
            *(float4*)(ra + 4) = *(const float4*)(&Qs[d*132 + 64 + ty*4]);
            *(float4*)(rb)     = *(const float4*)(&Kts[d*132 + tx*4]);
            *(float4*)(rb + 4) = *(const float4*)(&Kts[d*132 + 64 + tx*4]);
            #pragma unroll
            for (int i = 0; i < 8; i++)
                #pragma unroll
                for (int j = 0; j < 8; j++)
                    s[i][j] = fmaf(ra[i], rb[j], s[i][j]);
        }

        // causal mask on diagonal tile
        if (t == qt) {
            #pragma unroll
            for (int i = 0; i < 8; i++) {
                int qg = (i < 4) ? (ty*4 + i) : (64 + ty*4 + i - 4);
                #pragma unroll
                for (int j = 0; j < 8; j++) {
                    int kg = (j < 4) ? (tx*4 + j) : (64 + tx*4 + j - 4);
                    if (kg > qg) s[i][j] = -1e30f;
                }
            }
        }

        // online softmax, rows distributed over 16-lane groups (same ty)
        #pragma unroll
        for (int i = 0; i < 8; i++) {
            float mx = s[i][0];
            #pragma unroll
            for (int j = 1; j < 8; j++) mx = fmaxf(mx, s[i][j]);
            #pragma unroll
            for (int off = 1; off < 16; off <<= 1)
                mx = fmaxf(mx, __shfl_xor_sync(0xffffffffu, mx, off, 16));
            float al = __expf(mrow[i] - mx);   // first tile: exp(-inf)=0
            mrow[i] = mx;
            float ls = 0.f;
            #pragma unroll
            for (int j = 0; j < 8; j++) {
                float p = __expf(s[i][j] - mx);
                s[i][j] = p;
                ls += p;
            }
            #pragma unroll
            for (int off = 1; off < 16; off <<= 1)
                ls += __shfl_xor_sync(0xffffffffu, ls, off, 16);
            lrow[i] = lrow[i] * al + ls;
            #pragma unroll
            for (int jd = 0; jd < 4; jd++) o[i][jd] *= al;
        }

        // stage P as [k][q] (float4 along q)
        #pragma unroll
        for (int j = 0; j < 8; j++) {
            int kc = (j < 4) ? (tx*4 + j) : (64 + tx*4 + j - 4);
            *(float4*)(&Ps[kc*132 + ty*4]) =
                make_float4(s[0][j], s[1][j], s[2][j], s[3][j]);
            *(float4*)(&Ps[kc*132 + 64 + ty*4]) =
                make_float4(s[4][j], s[5][j], s[6][j], s[7][j]);
        }
        __syncthreads();

        // PV: o[q][d] += P[k][q] * V[k][d]
        #pragma unroll 4
        for (int kk = 0; kk < 128; kk++) {
            float4 pa = *(const float4*)(&Ps[kk*132 + ty*4]);        // broadcast
            float4 pb = *(const float4*)(&Ps[kk*132 + 64 + ty*4]);   // broadcast
            float4 vv = *(const float4*)(&Vs[kk*64 + tx*4]);
            o[0][0]=fmaf(pa.x,vv.x,o[0][0]); o[0][1]=fmaf(pa.x,vv.y,o[0][1]); o[0][2]=fmaf(pa.x,vv.z,o[0][2]); o[0][3]=fmaf(pa.x,vv.w,o[0][3]);
            o[1][0]=fmaf(pa.y,vv.x,o[1][0]); o[1][1]=fmaf(pa.y,vv.y,o[1][1]); o[1][2]=fmaf(pa.y,vv.z,o[1][2]); o[1][3]=fmaf(pa.y,vv.w,o[1][3]);
            o[2][0]=fmaf(pa.z,vv.x,o[2][0]); o[2][1]=fmaf(pa.z,vv.y,o[2][1]); o[2][2]=fmaf(pa.z,vv.z,o[2][2]); o[2][3]=fmaf(pa.z,vv.w,o[2][3]);
            o[3][0]=fmaf(pa.w,vv.x,o[3][0]); o[3][1]=fmaf(pa.w,vv.y,o[3][1]); o[3][2]=fmaf(pa.w,vv.z,o[3][2]); o[3][3]=fmaf(pa.w,vv.w,o[3][3]);
            o[4][0]=fmaf(pb.x,vv.x,o[4][0]); o[4][1]=fmaf(pb.x,vv.y,o[4][1]); o[4][2]=fmaf(pb.x,vv.z,o[4][2]); o[4][3]=fmaf(pb.x,vv.w,o[4][3]);
            o[5][0]=fmaf(pb.y,vv.x,o[5][0]); o[5][1]=fmaf(pb.y,vv.y,o[5][1]); o[5][2]=fmaf(pb.y,vv.z,o[5][2]); o[5][3]=fmaf(pb.y,vv.w,o[5][3]);
            o[6][0]=fmaf(pb.z,vv.x,o[6][0]); o[6][1]=fmaf(pb.z,vv.y,o[6][1]); o[6][2]=fmaf(pb.z,vv.z,o[6][2]); o[6][3]=fmaf(pb.z,vv.w,o[6][3]);
            o[7][0]=fmaf(pb.w,vv.x,o[7][0]); o[7][1]=fmaf(pb.w,vv.y,o[7][1]); o[7][2]=fmaf(pb.w,vv.z,o[7][2]); o[7][3]=fmaf(pb.w,vv.w,o[7][3]);
        }
    }

    // epilogue: normalize, write merged-head layout [B,S,E]
    #pragma unroll
    for (int i = 0; i < 8; i++) {
        int qr = (i < 4) ? (ty*4 + i) : (64 + ty*4 + i - 4);
        int qg = q0 + qr;
        float inv = 1.f / lrow[i];
        float4 r = make_float4(o[i][0]*inv, o[i][1]*inv, o[i][2]*inv, o[i][3]*inv);
        *(float4*)(O + ((size_t)b * Sq + qg) * Ee + hh * Dd + tx*4) = r;
    }
}

// ---------------------------------------------------------------------------
extern "C" void kernel_launch(void* const* d_in, const int* in_sizes, int n_in,
                              void* d_out, int out_size)
{
    const float* x      = (const float*)d_in[0];
    const float* W_attn = (const float*)d_in[1];
    const float* b_attn = (const float*)d_in[2];
    const float* W_proj = (const float*)d_in[3];
    const float* b_proj = (const float*)d_in[4];
    // d_in[5] = causal tril mask (int32) -- causality applied analytically
    float* out = (float*)d_out;

    float *qp, *kp, *vp, *op;
    cudaGetSymbolAddress((void**)&qp, g_q);
    cudaGetSymbolAddress((void**)&kp, g_k);
    cudaGetSymbolAddress((void**)&vp, g_v);
    cudaGetSymbolAddress((void**)&op, g_o);

    cudaFuncSetAttribute(attn_kernel,
                         cudaFuncAttributeMaxDynamicSharedMemorySize, ATTN_SMEM);

    // 1) Fused QKV projection, scatter into [B,H,S,D] q/k/v
    dim3 g1((3 * Ee) / 128, Mrows / 128);
    sgemm_kernel<1><<<g1, 256>>>(x, W_attn, b_attn, nullptr,
                                 qp, kp, vp, Mrows, 3 * Ee, Ee);

    // 2) Causal attention -> merged heads [B,S,E]
    attn_kernel<<<dim3(Sq / 128, Bb * Hh), 256, ATTN_SMEM>>>(qp, kp, vp, op);

    // 3) Output projection
    dim3 g2(Ee / 128, Mrows / 128);
    sgemm_kernel<0><<<g2, 256>>>(op, W_proj, b_proj, out,
                                 nullptr, nullptr, nullptr, Mrows, Ee, Ee);
}

// round 4
// speedup vs baseline: 2.9336x; 2.0697x over previous
#include <cuda_runtime.h>
#include <cuda_bf16.h>
#include <cstdint>

// Problem constants
#define Bb 2
#define Sq 2048
#define Ee 1024
#define Hh 16
#define Dd 64
#define Mrows (Bb*Sq)   // 4096

// Scratch (device globals: allocation-free, graph-capturable)
__device__ __nv_bfloat16 g_xh[(size_t)Mrows*Ee],  g_xl[(size_t)Mrows*Ee];
__device__ __nv_bfloat16 g_wah[(size_t)3*Ee*Ee],  g_wal[(size_t)3*Ee*Ee];
__device__ __nv_bfloat16 g_wph[(size_t)Ee*Ee],    g_wpl[(size_t)Ee*Ee];
__device__ __nv_bfloat16 g_qh[(size_t)Bb*Hh*Sq*Dd], g_ql[(size_t)Bb*Hh*Sq*Dd];
__device__ __nv_bfloat16 g_kh[(size_t)Bb*Hh*Sq*Dd], g_kl[(size_t)Bb*Hh*Sq*Dd];
__device__ __nv_bfloat16 g_vth[(size_t)Bb*Hh*Dd*Sq], g_vtl[(size_t)Bb*Hh*Dd*Sq]; // [bh][d][s]
__device__ __nv_bfloat16 g_oh[(size_t)Mrows*Ee],  g_ol[(size_t)Mrows*Ee];

// ---------------------------------------------------------------------------
// helpers (all plain sm_80-era PTX: valid on compute_103 virtual arch)
// ---------------------------------------------------------------------------
__device__ __forceinline__ uint32_t smem_u32(const void* p) {
    uint32_t a;
    asm("{ .reg .u64 t; cvta.to.shared.u64 t, %1; cvt.u32.u64 %0, t; }"
        : "=r"(a) : "l"(p));
    return a;
}
#define CPA(dst, src) \
    asm volatile("cp.async.cg.shared.global [%0], [%1], 16;" :: "r"(dst), "l"(src))
#define CP_COMMIT() asm volatile("cp.async.commit_group;")
#define CP_WAIT1()  asm volatile("cp.async.wait_group 1;" ::: "memory")
#define CP_WAIT0()  asm volatile("cp.async.wait_group 0;" ::: "memory")

__device__ __forceinline__ void mma_bf16(float* c, const uint32_t* a,
                                         uint32_t b0, uint32_t b1) {
    asm volatile(
        "mma.sync.aligned.m16n8k16.row.col.f32.bf16.bf16.f32 "
        "{%0,%1,%2,%3}, {%4,%5,%6,%7}, {%8,%9}, {%0,%1,%2,%3};"
        : "+f"(c[0]), "+f"(c[1]), "+f"(c[2]), "+f"(c[3])
        : "r"(a[0]), "r"(a[1]), "r"(a[2]), "r"(a[3]), "r"(b0), "r"(b1));
}

__device__ __forceinline__ void hsplit(float v, __nv_bfloat16& h, __nv_bfloat16& l) {
    h = __float2bfloat16(v);
    l = __float2bfloat16(v - __bfloat162float(h));
}
__device__ __forceinline__ uint32_t pack2(__nv_bfloat16 lo, __nv_bfloat16 hi) {
    __nv_bfloat162 t(lo, hi);       // x = lo (low 16 bits), y = hi
    return *(uint32_t*)&t;
}

// ---------------------------------------------------------------------------
// fp32 -> (hi, lo) bf16 pair conversion
// ---------------------------------------------------------------------------
__global__ __launch_bounds__(256)
void conv_kernel(const float* __restrict__ src, __nv_bfloat16* __restrict__ hi,
                 __nv_bfloat16* __restrict__ lo, int n)
{
    int i = (blockIdx.x * 256 + threadIdx.x) * 4;
    if (i >= n) return;
    float4 v = *(const float4*)(src + i);
    __nv_bfloat16 h0, h1, h2, h3, l0, l1, l2, l3;
    hsplit(v.x, h0, l0); hsplit(v.y, h1, l1);
    hsplit(v.z, h2, l2); hsplit(v.w, h3, l3);
    ((__nv_bfloat162*)(hi + i))[0] = __nv_bfloat162(h0, h1);
    ((__nv_bfloat162*)(hi + i))[1] = __nv_bfloat162(h2, h3);
    ((__nv_bfloat162*)(lo + i))[0] = __nv_bfloat162(l0, l1);
    ((__nv_bfloat162*)(lo + i))[1] = __nv_bfloat162(l2, l3);
}

// ---------------------------------------------------------------------------
// GEMM via mma.sync bf16 pairs: C[M,N] = (Ah+Al)(Bh+Bl)^T + bias
// 128x128 CTA tile, 8 warps (warp tile 32x64), K-chunk 32, cp.async 2-stage.
// SCATTER=1: write bf16 q(scaled)/k hi,lo + V^T hi,lo; SCATTER=0: fp32 C.
// smem stage: Ah,Al,Bh,Bl each [128][40] bf16 (10240B), stage = 40960B.
// ---------------------------------------------------------------------------
#define GST   40960
#define GSMEM (2*GST)

template<int SCATTER>
__global__ __launch_bounds__(256)
void gemm_mma(const __nv_bfloat16* __restrict__ Ahg, const __nv_bfloat16* __restrict__ Alg,
              const __nv_bfloat16* __restrict__ Bhg, const __nv_bfloat16* __restrict__ Blg,
              const float* __restrict__ bias, float* __restrict__ C,
              __nv_bfloat16* __restrict__ Qh, __nv_bfloat16* __restrict__ Ql,
              __nv_bfloat16* __restrict__ Kh, __nv_bfloat16* __restrict__ Kl,
              __nv_bfloat16* __restrict__ Vth, __nv_bfloat16* __restrict__ Vtl,
              int M, int N, int K)
{
    extern __shared__ __align__(16) char smg[];
    uint32_t sb = smem_u32(smg);
    int tid = threadIdx.x;
    int lane = tid & 31, warp = tid >> 5;
    int wm = warp >> 1, wn = warp & 1;
    int g = lane >> 2, t2 = (lane & 3) * 2;
    int m0 = blockIdx.y * 128, n0 = blockIdx.x * 128;

    const __nv_bfloat16* srcs[4] = {
        Ahg + (size_t)m0 * K, Alg + (size_t)m0 * K,
        Bhg + (size_t)n0 * K, Blg + (size_t)n0 * K };

    auto load_chunk = [&](int kt, int st) {
        uint32_t stb = sb + st * GST;
        #pragma unroll
        for (int b = 0; b < 4; b++) {
            const __nv_bfloat16* base = srcs[b] + kt;
            #pragma unroll
            for (int it = 0; it < 2; it++) {
                int idx = tid + it * 256;            // 0..511
                int r = idx >> 2, cg = idx & 3;      // 128 rows x 4 chunks(16B)
                CPA(stb + b * 10240 + r * 80 + cg * 16,
                    base + (size_t)r * K + cg * 8);
            }
        }
        CP_COMMIT();
    };

    float acc[2][8][4] = {};
    load_chunk(0, 0);
    int nch = K >> 5;
    for (int c = 0; c < nch; c++) {
        if (c + 1 < nch) { load_chunk((c + 1) * 32, (c + 1) & 1); CP_WAIT1(); }
        else             { CP_WAIT0(); }
        __syncthreads();
        const __nv_bfloat16* Ah = (const __nv_bfloat16*)(smg + (c & 1) * GST);
        const __nv_bfloat16* Al = Ah + 5120;
        const __nv_bfloat16* Bh = Ah + 10240;
        const __nv_bfloat16* Bl = Ah + 15360;
        #pragma unroll
        for (int kk = 0; kk < 32; kk += 16) {
            uint32_t aH[2][4], aL[2][4];
            #pragma unroll
            for (int i = 0; i < 2; i++) {
                int rb = wm * 32 + i * 16;
                aH[i][0] = *(const uint32_t*)&Ah[(rb+g  )*40 + kk     + t2];
                aH[i][1] = *(const uint32_t*)&Ah[(rb+g+8)*40 + kk     + t2];
                aH[i][2] = *(const uint32_t*)&Ah[(rb+g  )*40 + kk + 8 + t2];
                aH[i][3] = *(const uint32_t*)&Ah[(rb+g+8)*40 + kk + 8 + t2];
                aL[i][0] = *(const uint32_t*)&Al[(rb+g  )*40 + kk     + t2];
                aL[i][1] = *(const uint32_t*)&Al[(rb+g+8)*40 + kk     + t2];
                aL[i][2] = *(const uint32_t*)&Al[(rb+g  )*40 + kk + 8 + t2];
                aL[i][3] = *(const uint32_t*)&Al[(rb+g+8)*40 + kk + 8 + t2];
            }
            #pragma unroll
            for (int j = 0; j < 8; j++) {
                int nb = wn * 64 + j * 8;
                uint32_t bh0 = *(const uint32_t*)&Bh[(nb+g)*40 + kk     + t2];
                uint32_t bh1 = *(const uint32_t*)&Bh[(nb+g)*40 + kk + 8 + t2];
                uint32_t bl0 = *(const uint32_t*)&Bl[(nb+g)*40 + kk     + t2];
                uint32_t bl1 = *(const uint32_t*)&Bl[(nb+g)*40 + kk + 8 + t2];
                #pragma unroll
                for (int i = 0; i < 2; i++) {
                    mma_bf16(acc[i][j], aH[i], bh0, bh1);
                    mma_bf16(acc[i][j], aH[i], bl0, bl1);
                    mma_bf16(acc[i][j], aL[i], bh0, bh1);
                }
            }
        }
        __syncthreads();
    }

    // epilogue
    #pragma unroll
    for (int i = 0; i < 2; i++) {
        #pragma unroll
        for (int e2 = 0; e2 < 2; e2++) {
            int m = m0 + wm * 32 + i * 16 + g + e2 * 8;
            #pragma unroll
            for (int j = 0; j < 8; j++) {
                int n = n0 + wn * 64 + j * 8 + t2;
                float v0 = acc[i][j][e2*2+0] + bias[n];
                float v1 = acc[i][j][e2*2+1] + bias[n+1];
                if (SCATTER == 0) {
                    *(float2*)(C + (size_t)m * N + n) = make_float2(v0, v1);
                } else {
                    int part = n >> 10, e = n & 1023, hh = e >> 6, d = e & 63;
                    int b = m >> 11, s = m & 2047;
                    int bh = b * Hh + hh;
                    if (part == 0) { v0 *= 0.125f; v1 *= 0.125f; }
                    __nv_bfloat16 h0, l0, h1, l1;
                    hsplit(v0, h0, l0); hsplit(v1, h1, l1);
                    if (part < 2) {
                        size_t i0 = ((size_t)bh * Sq + s) * Dd + d;
                        __nv_bfloat16* dh = (part == 0 ? Qh : Kh) + i0;
                        __nv_bfloat16* dl = (part == 0 ? Ql : Kl) + i0;
                        *(__nv_bfloat162*)dh = __nv_bfloat162(h0, h1);
                        *(__nv_bfloat162*)dl = __nv_bfloat162(l0, l1);
                    } else {
                        size_t i0 = ((size_t)bh * Dd + d) * Sq + s;
                        Vth[i0] = h0; Vth[i0 + Sq] = h1;
                        Vtl[i0] = l0; Vtl[i0 + Sq] = l1;
                    }
                }
            }
        }
    }
}

// ---------------------------------------------------------------------------
// Flash attention on mma.sync bf16 pairs.
// CTA: 128 q rows, 8 warps (16 q rows each). Key tiles of 64, cp.async 2-stage.
// QK = Qh*Kh + Qh*Kl + Ql*Kh ; PV = Ph*Vh + Ph*Vl + Pl*Vh.
// smem: Qh,Ql [128][72]; per stage Kh,Kl [64][72], Vth,Vtl [64][72].
// ---------------------------------------------------------------------------
#define AST0  36864
#define ASTG  36864
#define ASMEM (AST0 + 2*ASTG)   // 110592

__global__ __launch_bounds__(256)
void attn_mma(const __nv_bfloat16* __restrict__ Qhg, const __nv_bfloat16* __restrict__ Qlg,
              const __nv_bfloat16* __restrict__ Khg, const __nv_bfloat16* __restrict__ Klg,
              const __nv_bfloat16* __restrict__ Vhg, const __nv_bfloat16* __restrict__ Vlg,
              __nv_bfloat16* __restrict__ Oh, __nv_bfloat16* __restrict__ Ol)
{
    extern __shared__ __align__(16) char sma[];
    uint32_t sb = smem_u32(sma);
    int tid = threadIdx.x, lane = tid & 31, w = tid >> 5;
    int g = lane >> 2, t2 = (lane & 3) * 2;
    int bh = blockIdx.y;
    int qt = gridDim.x - 1 - (int)blockIdx.x;   // heavy q-tiles first
    int q0 = qt * 128;

    const __nv_bfloat16* Khb = Khg + (size_t)bh * Sq * Dd;
    const __nv_bfloat16* Klb = Klg + (size_t)bh * Sq * Dd;
    const __nv_bfloat16* Vhb = Vhg + (size_t)bh * Dd * Sq;
    const __nv_bfloat16* Vlb = Vlg + (size_t)bh * Dd * Sq;

    // Q tiles -> smem (group 0)
    {
        const __nv_bfloat16* q0p = Qhg + ((size_t)bh * Sq + q0) * Dd;
        const __nv_bfloat16* q1p = Qlg + ((size_t)bh * Sq + q0) * Dd;
        #pragma unroll
        for (int it = 0; it < 4; it++) {
            int idx = tid + it * 256;           // 0..1023
            int r = idx >> 3, cg = idx & 7;     // 128 rows x 8 chunks
            CPA(sb + r * 144 + cg * 16,         q0p + (size_t)r * Dd + cg * 8);
            CPA(sb + 18432 + r * 144 + cg * 16, q1p + (size_t)r * Dd + cg * 8);
        }
        CP_COMMIT();
    }

    auto load_tile = [&](int t, int st) {
        uint32_t stb = sb + AST0 + st * ASTG;
        int k0 = t * 64;
        #pragma unroll
        for (int it = 0; it < 2; it++) {
            int idx = tid + it * 256;           // 0..511
            int r = idx >> 3, cg = idx & 7;     // 64 rows x 8 chunks
            CPA(stb +         r * 144 + cg * 16, Khb + (size_t)(k0 + r) * Dd + cg * 8);
            CPA(stb +  9216 + r * 144 + cg * 16, Klb + (size_t)(k0 + r) * Dd + cg * 8);
            CPA(stb + 18432 + r * 144 + cg * 16, Vhb + (size_t)r * Sq + k0 + cg * 8);
            CPA(stb + 27648 + r * 144 + cg * 16, Vlb + (size_t)r * Sq + k0 + cg * 8);
        }
        CP_COMMIT();
    };

    int T = 2 * qt + 2;
    load_tile(0, 0);

    float o[8][4] = {};
    float m0r = -1e30f, m1r = -1e30f, l0 = 0.f, l1 = 0.f;
    int qwmin = q0 + w * 16;

    for (int t = 0; t < T; t++) {
        if (t + 1 < T) { load_tile(t + 1, (t + 1) & 1); CP_WAIT1(); }
        else           { CP_WAIT0(); }
        __syncthreads();

        if (64 * t <= qwmin + 15) {
            const __nv_bfloat16* Kh = (const __nv_bfloat16*)(sma + AST0 + (t & 1) * ASTG);
            const __nv_bfloat16* Kl = Kh + 4608;
            const __nv_bfloat16* Vh = Kh + 9216;
            const __nv_bfloat16* Vl = Kh + 13824;
            const __nv_bfloat16* Qs = (const __nv_bfloat16*)sma;
            const __nv_bfloat16* Qg = Qs + 9216;

            // ---- QK ----
            float s[8][4] = {};
            int rb = w * 16;
            #pragma unroll
            for (int ks = 0; ks < 4; ks++) {
                int kk = ks * 16;
                uint32_t aH[4], aL[4];
                aH[0] = *(const uint32_t*)&Qs[(rb+g  )*72 + kk     + t2];
                aH[1] = *(const uint32_t*)&Qs[(rb+g+8)*72 + kk     + t2];
                aH[2] = *(const uint32_t*)&Qs[(rb+g  )*72 + kk + 8 + t2];
                aH[3] = *(const uint32_t*)&Qs[(rb+g+8)*72 + kk + 8 + t2];
                aL[0] = *(const uint32_t*)&Qg[(rb+g  )*72 + kk     + t2];
                aL[1] = *(const uint32_t*)&Qg[(rb+g+8)*72 + kk     + t2];
                aL[2] = *(const uint32_t*)&Qg[(rb+g  )*72 + kk + 8 + t2];
                aL[3] = *(const uint32_t*)&Qg[(rb+g+8)*72 + kk + 8 + t2];
                #pragma unroll
                for (int j = 0; j < 8; j++) {
                    uint32_t bh0 = *(const uint32_t*)&Kh[(j*8+g)*72 + kk     + t2];
                    uint32_t bh1 = *(const uint32_t*)&Kh[(j*8+g)*72 + kk + 8 + t2];
                    uint32_t bl0 = *(const uint32_t*)&Kl[(j*8+g)*72 + kk     + t2];
                    uint32_t bl1 = *(const uint32_t*)&Kl[(j*8+g)*72 + kk + 8 + t2];
                    mma_bf16(s[j], aH, bh0, bh1);
                    mma_bf16(s[j], aH, bl0, bl1);
                    mma_bf16(s[j], aL, bh0, bh1);
                }
            }

            // ---- causal mask ----
            if (64 * t + 63 > qwmin) {
                int qr0 = qwmin + g, qr1 = qwmin + g + 8;
                #pragma unroll
                for (int j = 0; j < 8; j++) {
                    int kb = 64 * t + j * 8 + t2;
                    if (kb     > qr0) s[j][0] = -1e30f;
                    if (kb + 1 > qr0) s[j][1] = -1e30f;
                    if (kb     > qr1) s[j][2] = -1e30f;
                    if (kb + 1 > qr1) s[j][3] = -1e30f;
                }
            }

            // ---- online softmax ----
            float mx0 = -1e30f, mx1 = -1e30f;
            #pragma unroll
            for (int j = 0; j < 8; j++) {
                mx0 = fmaxf(mx0, fmaxf(s[j][0], s[j][1]));
                mx1 = fmaxf(mx1, fmaxf(s[j][2], s[j][3]));
            }
            #pragma unroll
            for (int off = 1; off < 4; off <<= 1) {
                mx0 = fmaxf(mx0, __shfl_xor_sync(0xffffffffu, mx0, off, 4));
                mx1 = fmaxf(mx1, __shfl_xor_sync(0xffffffffu, mx1, off, 4));
            }
            mx0 = fmaxf(mx0, m0r);
            mx1 = fmaxf(mx1, m1r);
            float al0 = __expf(m0r - mx0), al1 = __expf(m1r - mx1);
            m0r = mx0; m1r = mx1;
            l0 *= al0;  l1 *= al1;
            #pragma unroll
            for (int j = 0; j < 8; j++) {
                s[j][0] = __expf(s[j][0] - mx0);
                s[j][1] = __expf(s[j][1] - mx0);
                s[j][2] = __expf(s[j][2] - mx1);
                s[j][3] = __expf(s[j][3] - mx1);
                l0 += s[j][0] + s[j][1];
                l1 += s[j][2] + s[j][3];
                o[j][0] *= al0; o[j][1] *= al0;
                o[j][2] *= al1; o[j][3] *= al1;
            }

            // ---- PV ----
            #pragma unroll
            for (int ks = 0; ks < 4; ks++) {
                int j0 = 2 * ks, j1 = 2 * ks + 1;
                __nv_bfloat16 h, l;
                uint32_t pH[4], pL[4];
                __nv_bfloat16 h2, l2;
                hsplit(s[j0][0], h, l); hsplit(s[j0][1], h2, l2);
                pH[0] = pack2(h, h2); pL[0] = pack2(l, l2);
                hsplit(s[j0][2], h, l); hsplit(s[j0][3], h2, l2);
                pH[1] = pack2(h, h2); pL[1] = pack2(l, l2);
                hsplit(s[j1][0], h, l); hsplit(s[j1][1], h2, l2);
                pH[2] = pack2(h, h2); pL[2] = pack2(l, l2);
                hsplit(s[j1][2], h, l); hsplit(s[j1][3], h2, l2);
                pH[3] = pack2(h, h2); pL[3] = pack2(l, l2);
                #pragma unroll
                for (int j = 0; j < 8; j++) {
                    uint32_t vh0 = *(const uint32_t*)&Vh[(j*8+g)*72 + ks*16     + t2];
                    uint32_t vh1 = *(const uint32_t*)&Vh[(j*8+g)*72 + ks*16 + 8 + t2];
                    uint32_t vl0 = *(const uint32_t*)&Vl[(j*8+g)*72 + ks*16     + t2];
                    uint32_t vl1 = *(const uint32_t*)&Vl[(j*8+g)*72 + ks*16 + 8 + t2];
                    mma_bf16(o[j], pH, vh0, vh1);
                    mma_bf16(o[j], pH, vl0, vl1);
                    mma_bf16(o[j], pL, vh0, vh1);
                }
            }
        }
        __syncthreads();
    }

    // ---- finalize ----
    #pragma unroll
    for (int off = 1; off < 4; off <<= 1) {
        l0 += __shfl_xor_sync(0xffffffffu, l0, off, 4);
        l1 += __shfl_xor_sync(0xffffffffu, l1, off, 4);
    }
    float inv0 = 1.f / l0, inv1 = 1.f / l1;
    int b = bh >> 4, hh = bh & 15;
    int r0 = q0 + w * 16 + g, r1 = r0 + 8;
    #pragma unroll
    for (int j = 0; j < 8; j++) {
        int d = j * 8 + t2;
        __nv_bfloat16 h0, l0b, h1, l1b;
        size_t i0 = ((size_t)(b * Sq + r0)) * Ee + hh * Dd + d;
        hsplit(o[j][0] * inv0, h0, l0b); hsplit(o[j][1] * inv0, h1, l1b);
        *(__nv_bfloat162*)(Oh + i0) = __nv_bfloat162(h0, h1);
        *(__nv_bfloat162*)(Ol + i0) = __nv_bfloat162(l0b, l1b);
        size_t i1 = ((size_t)(b * Sq + r1)) * Ee + hh * Dd + d;
        hsplit(o[j][2] * inv1, h0, l0b); hsplit(o[j][3] * inv1, h1, l1b);
        *(__nv_bfloat162*)(Oh + i1) = __nv_bfloat162(h0, h1);
        *(__nv_bfloat162*)(Ol + i1) = __nv_bfloat162(l0b, l1b);
    }
}

// ---------------------------------------------------------------------------
extern "C" void kernel_launch(void* const* d_in, const int* in_sizes, int n_in,
                              void* d_out, int out_size)
{
    const float* x      = (const float*)d_in[0];
    const float* W_attn = (const float*)d_in[1];
    const float* b_attn = (const float*)d_in[2];
    const float* W_proj = (const float*)d_in[3];
    const float* b_proj = (const float*)d_in[4];
    float* out = (float*)d_out;

    __nv_bfloat16 *xh, *xl, *wah, *wal, *wph, *wpl;
    __nv_bfloat16 *qh, *ql, *kh, *kl, *vth, *vtl, *oh, *ol;
    cudaGetSymbolAddress((void**)&xh, g_xh);   cudaGetSymbolAddress((void**)&xl, g_xl);
    cudaGetSymbolAddress((void**)&wah, g_wah); cudaGetSymbolAddress((void**)&wal, g_wal);
    cudaGetSymbolAddress((void**)&wph, g_wph); cudaGetSymbolAddress((void**)&wpl, g_wpl);
    cudaGetSymbolAddress((void**)&qh, g_qh);   cudaGetSymbolAddress((void**)&ql, g_ql);
    cudaGetSymbolAddress((void**)&kh, g_kh);   cudaGetSymbolAddress((void**)&kl, g_kl);
    cudaGetSymbolAddress((void**)&vth, g_vth); cudaGetSymbolAddress((void**)&vtl, g_vtl);
    cudaGetSymbolAddress((void**)&oh, g_oh);   cudaGetSymbolAddress((void**)&ol, g_ol);

    cudaFuncSetAttribute(gemm_mma<0>, cudaFuncAttributeMaxDynamicSharedMemorySize, GSMEM);
    cudaFuncSetAttribute(gemm_mma<1>, cudaFuncAttributeMaxDynamicSharedMemorySize, GSMEM);
    cudaFuncSetAttribute(attn_mma,    cudaFuncAttributeMaxDynamicSharedMemorySize, ASMEM);

    // 0) fp32 -> bf16 hi/lo conversions
    conv_kernel<<<Mrows*Ee/1024, 256>>>(x, xh, xl, Mrows*Ee);
    conv_kernel<<<3*Ee*Ee/1024, 256>>>(W_attn, wah, wal, 3*Ee*Ee);
    conv_kernel<<<Ee*Ee/1024, 256>>>(W_proj, wph, wpl, Ee*Ee);

    // 1) QKV projection -> bf16 q(scaled)/k hi,lo + V^T hi,lo
    gemm_mma<1><<<dim3(3*Ee/128, Mrows/128), 256, GSMEM>>>(
        xh, xl, wah, wal, b_attn, nullptr,
        qh, ql, kh, kl, vth, vtl, Mrows, 3*Ee, Ee);

    // 2) Causal flash attention -> merged-head bf16 hi/lo
    attn_mma<<<dim3(Sq/128, Bb*Hh), 256, ASMEM>>>(qh, ql, kh, kl, vth, vtl, oh, ol);

    // 3) Output projection -> fp32 out
    gemm_mma<0><<<dim3(Ee/128, Mrows/128), 256, GSMEM>>>(
        oh, ol, wph, wpl, b_proj, out,
        nullptr, nullptr, nullptr, nullptr, nullptr, nullptr, Mrows, Ee, Ee);
}

// round 5
// speedup vs baseline: 3.3426x; 1.1394x over previous
#include <cuda_runtime.h>
#include <cuda_bf16.h>
#include <cstdint>

// Problem constants
#define Bb 2
#define Sq 2048
#define Ee 1024
#define Hh 16
#define Dd 64
#define Mrows (Bb*Sq)   // 4096

// Scratch (device globals: allocation-free, graph-capturable)
__device__ __nv_bfloat16 g_xh[(size_t)Mrows*Ee],  g_xl[(size_t)Mrows*Ee];
__device__ __nv_bfloat16 g_wah[(size_t)3*Ee*Ee],  g_wal[(size_t)3*Ee*Ee];
__device__ __nv_bfloat16 g_wph[(size_t)Ee*Ee],    g_wpl[(size_t)Ee*Ee];
__device__ __nv_bfloat16 g_qh[(size_t)Bb*Hh*Sq*Dd], g_ql[(size_t)Bb*Hh*Sq*Dd];
__device__ __nv_bfloat16 g_kh[(size_t)Bb*Hh*Sq*Dd], g_kl[(size_t)Bb*Hh*Sq*Dd];
__device__ __nv_bfloat16 g_vth[(size_t)Bb*Hh*Dd*Sq], g_vtl[(size_t)Bb*Hh*Dd*Sq]; // [bh][d][s]
__device__ __nv_bfloat16 g_oh[(size_t)Mrows*Ee],  g_ol[(size_t)Mrows*Ee];

// ---------------------------------------------------------------------------
// helpers (all plain sm_80-era PTX: valid on compute_103 virtual arch)
// ---------------------------------------------------------------------------
__device__ __forceinline__ uint32_t smem_u32(const void* p) {
    uint32_t a;
    asm("{ .reg .u64 t; cvta.to.shared.u64 t, %1; cvt.u32.u64 %0, t; }"
        : "=r"(a) : "l"(p));
    return a;
}
#define CPA(dst, src) \
    asm volatile("cp.async.cg.shared.global [%0], [%1], 16;" :: "r"(dst), "l"(src))
#define CP_COMMIT() asm volatile("cp.async.commit_group;")
#define CP_WAIT1()  asm volatile("cp.async.wait_group 1;" ::: "memory")
#define CP_WAIT0()  asm volatile("cp.async.wait_group 0;" ::: "memory")

#define LDSM4(r, addr) \
    asm volatile("ldmatrix.sync.aligned.m8n8.x4.shared.b16 {%0,%1,%2,%3}, [%4];" \
        : "=r"((r)[0]), "=r"((r)[1]), "=r"((r)[2]), "=r"((r)[3]) : "r"(addr))

__device__ __forceinline__ void mma_bf16(float* c, const uint32_t* a,
                                         uint32_t b0, uint32_t b1) {
    asm volatile(
        "mma.sync.aligned.m16n8k16.row.col.f32.bf16.bf16.f32 "
        "{%0,%1,%2,%3}, {%4,%5,%6,%7}, {%8,%9}, {%0,%1,%2,%3};"
        : "+f"(c[0]), "+f"(c[1]), "+f"(c[2]), "+f"(c[3])
        : "r"(a[0]), "r"(a[1]), "r"(a[2]), "r"(a[3]), "r"(b0), "r"(b1));
}

__device__ __forceinline__ void hsplit(float v, __nv_bfloat16& h, __nv_bfloat16& l) {
    h = __float2bfloat16(v);
    l = __float2bfloat16(v - __bfloat162float(h));
}
__device__ __forceinline__ uint32_t pack2(__nv_bfloat16 lo, __nv_bfloat16 hi) {
    __nv_bfloat162 t(lo, hi);
    return *(uint32_t*)&t;
}

// ---------------------------------------------------------------------------
// fp32 -> (hi, lo) bf16 pair conversion
// ---------------------------------------------------------------------------
__global__ __launch_bounds__(256)
void conv_kernel(const float* __restrict__ src, __nv_bfloat16* __restrict__ hi,
                 __nv_bfloat16* __restrict__ lo, int n)
{
    int i = (blockIdx.x * 256 + threadIdx.x) * 4;
    if (i >= n) return;
    float4 v = *(const float4*)(src + i);
    __nv_bfloat16 h0, h1, h2, h3, l0, l1, l2, l3;
    hsplit(v.x, h0, l0); hsplit(v.y, h1, l1);
    hsplit(v.z, h2, l2); hsplit(v.w, h3, l3);
    ((__nv_bfloat162*)(hi + i))[0] = __nv_bfloat162(h0, h1);
    ((__nv_bfloat162*)(hi + i))[1] = __nv_bfloat162(h2, h3);
    ((__nv_bfloat162*)(lo + i))[0] = __nv_bfloat162(l0, l1);
    ((__nv_bfloat162*)(lo + i))[1] = __nv_bfloat162(l2, l3);
}

// ---------------------------------------------------------------------------
// GEMM via mma.sync bf16 pairs: C[M,N] = (Ah+Al)(Bh+Bl)^T + bias
// 128x128 CTA tile, 8 warps (warp tile 32x64), K-chunk 32, cp.async 2-stage,
// ldmatrix.x4 fragment loads, 2 CTAs/SM.
// smem stage: Ah,Al,Bh,Bl each [128][40] bf16 (10240B), stage = 40960B.
// ---------------------------------------------------------------------------
#define GST   40960
#define GSMEM (2*GST)

template<int SCATTER>
__global__ __launch_bounds__(256, 2)
void gemm_mma(const __nv_bfloat16* __restrict__ Ahg, const __nv_bfloat16* __restrict__ Alg,
              const __nv_bfloat16* __restrict__ Bhg, const __nv_bfloat16* __restrict__ Blg,
              const float* __restrict__ bias, float* __restrict__ C,
              __nv_bfloat16* __restrict__ Qh, __nv_bfloat16* __restrict__ Ql,
              __nv_bfloat16* __restrict__ Kh, __nv_bfloat16* __restrict__ Kl,
              __nv_bfloat16* __restrict__ Vth, __nv_bfloat16* __restrict__ Vtl,
              int M, int N, int K)
{
    extern __shared__ __align__(16) char smg[];
    uint32_t sb = smem_u32(smg);
    int tid = threadIdx.x;
    int lane = tid & 31, warp = tid >> 5;
    int wm = warp >> 1, wn = warp & 1;
    int g = lane >> 2, t2 = (lane & 3) * 2;
    int m0 = blockIdx.y * 128, n0 = blockIdx.x * 128;

    // ldmatrix lane offsets (bytes, within a buffer of [128][40] bf16, 80B rows)
    uint32_t aOff = (uint32_t)((wm * 32 + (lane & 15)) * 80 + ((lane >> 4) << 3) * 2);
    uint32_t bOff = (uint32_t)((wn * 64 + ((lane >> 4) << 3) + (lane & 7)) * 80 +
                               (((lane >> 3) & 1) << 3) * 2);

    const __nv_bfloat16* srcs[4] = {
        Ahg + (size_t)m0 * K, Alg + (size_t)m0 * K,
        Bhg + (size_t)n0 * K, Blg + (size_t)n0 * K };

    auto load_chunk = [&](int kt, int st) {
        uint32_t stb = sb + st * GST;
        #pragma unroll
        for (int b = 0; b < 4; b++) {
            const __nv_bfloat16* base = srcs[b] + kt;
            #pragma unroll
            for (int it = 0; it < 2; it++) {
                int idx = tid + it * 256;            // 0..511
                int r = idx >> 2, cg = idx & 3;      // 128 rows x 4 chunks(16B)
                CPA(stb + b * 10240 + r * 80 + cg * 16,
                    base + (size_t)r * K + cg * 8);
            }
        }
        CP_COMMIT();
    };

    float acc[2][8][4] = {};
    load_chunk(0, 0);
    int nch = K >> 5;
    for (int c = 0; c < nch; c++) {
        if (c + 1 < nch) { load_chunk((c + 1) * 32, (c + 1) & 1); CP_WAIT1(); }
        else             { CP_WAIT0(); }
        __syncthreads();
        uint32_t stb = sb + (c & 1) * GST;
        #pragma unroll
        for (int kk = 0; kk < 32; kk += 16) {
            uint32_t aH[2][4], aL[2][4];
            LDSM4(aH[0], stb + aOff + kk * 2);
            LDSM4(aH[1], stb + aOff + kk * 2 + 16 * 80);
            LDSM4(aL[0], stb + 10240 + aOff + kk * 2);
            LDSM4(aL[1], stb + 10240 + aOff + kk * 2 + 16 * 80);
            #pragma unroll
            for (int j2 = 0; j2 < 4; j2++) {
                uint32_t bhf[4], blf[4];
                LDSM4(bhf, stb + 20480 + bOff + j2 * 1280 + kk * 2);
                LDSM4(blf, stb + 30720 + bOff + j2 * 1280 + kk * 2);
                #pragma unroll
                for (int i = 0; i < 2; i++) {
                    mma_bf16(acc[i][2*j2],   aH[i], bhf[0], bhf[1]);
                    mma_bf16(acc[i][2*j2],   aH[i], blf[0], blf[1]);
                    mma_bf16(acc[i][2*j2],   aL[i], bhf[0], bhf[1]);
                    mma_bf16(acc[i][2*j2+1], aH[i], bhf[2], bhf[3]);
                    mma_bf16(acc[i][2*j2+1], aH[i], blf[2], blf[3]);
                    mma_bf16(acc[i][2*j2+1], aL[i], bhf[2], bhf[3]);
                }
            }
        }
        __syncthreads();
    }

    // epilogue
    #pragma unroll
    for (int i = 0; i < 2; i++) {
        #pragma unroll
        for (int e2 = 0; e2 < 2; e2++) {
            int m = m0 + wm * 32 + i * 16 + g + e2 * 8;
            #pragma unroll
            for (int j = 0; j < 8; j++) {
                int n = n0 + wn * 64 + j * 8 + t2;
                float v0 = acc[i][j][e2*2+0] + bias[n];
                float v1 = acc[i][j][e2*2+1] + bias[n+1];
                if (SCATTER == 0) {
                    *(float2*)(C + (size_t)m * N + n) = make_float2(v0, v1);
                } else {
                    int part = n >> 10, e = n & 1023, hh = e >> 6, d = e & 63;
                    int b = m >> 11, s = m & 2047;
                    int bh = b * Hh + hh;
                    if (part == 0) { v0 *= 0.125f; v1 *= 0.125f; }
                    __nv_bfloat16 h0, l0, h1, l1;
                    hsplit(v0, h0, l0); hsplit(v1, h1, l1);
                    if (part < 2) {
                        size_t i0 = ((size_t)bh * Sq + s) * Dd + d;
                        __nv_bfloat16* dh = (part == 0 ? Qh : Kh) + i0;
                        __nv_bfloat16* dl = (part == 0 ? Ql : Kl) + i0;
                        *(__nv_bfloat162*)dh = __nv_bfloat162(h0, h1);
                        *(__nv_bfloat162*)dl = __nv_bfloat162(l0, l1);
                    } else {
                        size_t i0 = ((size_t)bh * Dd + d) * Sq + s;
                        Vth[i0] = h0; Vth[i0 + Sq] = h1;
                        Vtl[i0] = l0; Vtl[i0 + Sq] = l1;
                    }
                }
            }
        }
    }
}

// ---------------------------------------------------------------------------
// Flash attention on mma.sync bf16 pairs + ldmatrix fragment loads.
// CTA: 128 q rows, 8 warps (16 q rows each). Key tiles of 64, cp.async 2-stage.
// smem: Qh,Ql [128][72]; per stage Kh,Kl [64][72], Vth,Vtl [64][72].
// ---------------------------------------------------------------------------
#define AST0  36864
#define ASTG  36864
#define ASMEM (AST0 + 2*ASTG)   // 110592

__global__ __launch_bounds__(256, 2)
void attn_mma(const __nv_bfloat16* __restrict__ Qhg, const __nv_bfloat16* __restrict__ Qlg,
              const __nv_bfloat16* __restrict__ Khg, const __nv_bfloat16* __restrict__ Klg,
              const __nv_bfloat16* __restrict__ Vhg, const __nv_bfloat16* __restrict__ Vlg,
              __nv_bfloat16* __restrict__ Oh, __nv_bfloat16* __restrict__ Ol)
{
    extern __shared__ __align__(16) char sma[];
    uint32_t sb = smem_u32(sma);
    int tid = threadIdx.x, lane = tid & 31, w = tid >> 5;
    int g = lane >> 2, t2 = (lane & 3) * 2;
    int bh = blockIdx.y;
    int qt = gridDim.x - 1 - (int)blockIdx.x;   // heavy q-tiles first
    int q0 = qt * 128;

    // ldmatrix lane offsets (144B rows)
    uint32_t qOff = (uint32_t)((w * 16 + (lane & 15)) * 144 + ((lane >> 4) << 3) * 2);
    uint32_t kOff = (uint32_t)((((lane >> 4) << 3) + (lane & 7)) * 144 +
                               (((lane >> 3) & 1) << 3) * 2);

    const __nv_bfloat16* Khb = Khg + (size_t)bh * Sq * Dd;
    const __nv_bfloat16* Klb = Klg + (size_t)bh * Sq * Dd;
    const __nv_bfloat16* Vhb = Vhg + (size_t)bh * Dd * Sq;
    const __nv_bfloat16* Vlb = Vlg + (size_t)bh * Dd * Sq;

    // Q tiles -> smem (group 0)
    {
        const __nv_bfloat16* q0p = Qhg + ((size_t)bh * Sq + q0) * Dd;
        const __nv_bfloat16* q1p = Qlg + ((size_t)bh * Sq + q0) * Dd;
        #pragma unroll
        for (int it = 0; it < 4; it++) {
            int idx = tid + it * 256;           // 0..1023
            int r = idx >> 3, cg = idx & 7;     // 128 rows x 8 chunks
            CPA(sb + r * 144 + cg * 16,         q0p + (size_t)r * Dd + cg * 8);
            CPA(sb + 18432 + r * 144 + cg * 16, q1p + (size_t)r * Dd + cg * 8);
        }
        CP_COMMIT();
    }

    auto load_tile = [&](int t, int st) {
        uint32_t stb = sb + AST0 + st * ASTG;
        int k0 = t * 64;
        #pragma unroll
        for (int it = 0; it < 2; it++) {
            int idx = tid + it * 256;           // 0..511
            int r = idx >> 3, cg = idx & 7;     // 64 rows x 8 chunks
            CPA(stb +         r * 144 + cg * 16, Khb + (size_t)(k0 + r) * Dd + cg * 8);
            CPA(stb +  9216 + r * 144 + cg * 16, Klb + (size_t)(k0 + r) * Dd + cg * 8);
            CPA(stb + 18432 + r * 144 + cg * 16, Vhb + (size_t)r * Sq + k0 + cg * 8);
            CPA(stb + 27648 + r * 144 + cg * 16, Vlb + (size_t)r * Sq + k0 + cg * 8);
        }
        CP_COMMIT();
    };

    int T = 2 * qt + 2;
    load_tile(0, 0);

    float o[8][4] = {};
    float m0r = -1e30f, m1r = -1e30f, l0 = 0.f, l1 = 0.f;
    int qwmin = q0 + w * 16;

    for (int t = 0; t < T; t++) {
        if (t + 1 < T) { load_tile(t + 1, (t + 1) & 1); CP_WAIT1(); }
        else           { CP_WAIT0(); }
        __syncthreads();

        if (64 * t <= qwmin + 15) {
            uint32_t kb = sb + AST0 + (t & 1) * ASTG;

            // ---- QK ----
            float s[8][4] = {};
            #pragma unroll
            for (int ks = 0; ks < 4; ks++) {
                int kk = ks * 16;
                uint32_t aH[4], aL[4];
                LDSM4(aH, sb + qOff + kk * 2);
                LDSM4(aL, sb + 18432 + qOff + kk * 2);
                #pragma unroll
                for (int j2 = 0; j2 < 4; j2++) {
                    uint32_t bhf[4], blf[4];
                    LDSM4(bhf, kb +        kOff + j2 * 2304 + kk * 2);
                    LDSM4(blf, kb + 9216 + kOff + j2 * 2304 + kk * 2);
                    mma_bf16(s[2*j2],   aH, bhf[0], bhf[1]);
                    mma_bf16(s[2*j2],   aH, blf[0], blf[1]);
                    mma_bf16(s[2*j2],   aL, bhf[0], bhf[1]);
                    mma_bf16(s[2*j2+1], aH, bhf[2], bhf[3]);
                    mma_bf16(s[2*j2+1], aH, blf[2], blf[3]);
                    mma_bf16(s[2*j2+1], aL, bhf[2], bhf[3]);
                }
            }

            // ---- causal mask ----
            if (64 * t + 63 > qwmin) {
                int qr0 = qwmin + g, qr1 = qwmin + g + 8;
                #pragma unroll
                for (int j = 0; j < 8; j++) {
                    int kbi = 64 * t + j * 8 + t2;
                    if (kbi     > qr0) s[j][0] = -1e30f;
                    if (kbi + 1 > qr0) s[j][1] = -1e30f;
                    if (kbi     > qr1) s[j][2] = -1e30f;
                    if (kbi + 1 > qr1) s[j][3] = -1e30f;
                }
            }

            // ---- online softmax ----
            float mx0 = -1e30f, mx1 = -1e30f;
            #pragma unroll
            for (int j = 0; j < 8; j++) {
                mx0 = fmaxf(mx0, fmaxf(s[j][0], s[j][1]));
                mx1 = fmaxf(mx1, fmaxf(s[j][2], s[j][3]));
            }
            #pragma unroll
            for (int off = 1; off < 4; off <<= 1) {
                mx0 = fmaxf(mx0, __shfl_xor_sync(0xffffffffu, mx0, off, 4));
                mx1 = fmaxf(mx1, __shfl_xor_sync(0xffffffffu, mx1, off, 4));
            }
            mx0 = fmaxf(mx0, m0r);
            mx1 = fmaxf(mx1, m1r);
            float al0 = __expf(m0r - mx0), al1 = __expf(m1r - mx1);
            m0r = mx0; m1r = mx1;
            l0 *= al0;  l1 *= al1;
            #pragma unroll
            for (int j = 0; j < 8; j++) {
                s[j][0] = __expf(s[j][0] - mx0);
                s[j][1] = __expf(s[j][1] - mx0);
                s[j][2] = __expf(s[j][2] - mx1);
                s[j][3] = __expf(s[j][3] - mx1);
                l0 += s[j][0] + s[j][1];
                l1 += s[j][2] + s[j][3];
                o[j][0] *= al0; o[j][1] *= al0;
                o[j][2] *= al1; o[j][3] *= al1;
            }

            // ---- PV ----
            #pragma unroll
            for (int ks = 0; ks < 4; ks++) {
                int j0 = 2 * ks, j1 = 2 * ks + 1;
                __nv_bfloat16 h, l, h2, l2;
                uint32_t pH[4], pL[4];
                hsplit(s[j0][0], h, l); hsplit(s[j0][1], h2, l2);
                pH[0] = pack2(h, h2); pL[0] = pack2(l, l2);
                hsplit(s[j0][2], h, l); hsplit(s[j0][3], h2, l2);
                pH[1] = pack2(h, h2); pL[1] = pack2(l, l2);
                hsplit(s[j1][0], h, l); hsplit(s[j1][1], h2, l2);
                pH[2] = pack2(h, h2); pL[2] = pack2(l, l2);
                hsplit(s[j1][2], h, l); hsplit(s[j1][3], h2, l2);
                pH[3] = pack2(h, h2); pL[3] = pack2(l, l2);
                #pragma unroll
                for (int j2 = 0; j2 < 4; j2++) {
                    uint32_t vhf[4], vlf[4];
                    LDSM4(vhf, kb + 18432 + kOff + j2 * 2304 + ks * 32);
                    LDSM4(vlf, kb + 27648 + kOff + j2 * 2304 + ks * 32);
                    mma_bf16(o[2*j2],   pH, vhf[0], vhf[1]);
                    mma_bf16(o[2*j2],   pH, vlf[0], vlf[1]);
                    mma_bf16(o[2*j2],   pL, vhf[0], vhf[1]);
                    mma_bf16(o[2*j2+1], pH, vhf[2], vhf[3]);
                    mma_bf16(o[2*j2+1], pH, vlf[2], vlf[3]);
                    mma_bf16(o[2*j2+1], pL, vhf[2], vhf[3]);
                }
            }
        }
        __syncthreads();
    }

    // ---- finalize ----
    #pragma unroll
    for (int off = 1; off < 4; off <<= 1) {
        l0 += __shfl_xor_sync(0xffffffffu, l0, off, 4);
        l1 += __shfl_xor_sync(0xffffffffu, l1, off, 4);
    }
    float inv0 = 1.f / l0, inv1 = 1.f / l1;
    int b = bh >> 4, hh = bh & 15;
    int r0 = q0 + w * 16 + g, r1 = r0 + 8;
    #pragma unroll
    for (int j = 0; j < 8; j++) {
        int d = j * 8 + t2;
        __nv_bfloat16 h0, l0b, h1, l1b;
        size_t i0 = ((size_t)(b * Sq + r0)) * Ee + hh * Dd + d;
        hsplit(o[j][0] * inv0, h0, l0b); hsplit(o[j][1] * inv0, h1, l1b);
        *(__nv_bfloat162*)(Oh + i0) = __nv_bfloat162(h0, h1);
        *(__nv_bfloat162*)(Ol + i0) = __nv_bfloat162(l0b, l1b);
        size_t i1 = ((size_t)(b * Sq + r1)) * Ee + hh * Dd + d;
        hsplit(o[j][2] * inv1, h0, l0b); hsplit(o[j][3] * inv1, h1, l1b);
        *(__nv_bfloat162*)(Oh + i1) = __nv_bfloat162(h0, h1);
        *(__nv_bfloat162*)(Ol + i1) = __nv_bfloat162(l0b, l1b);
    }
}

// ---------------------------------------------------------------------------
extern "C" void kernel_launch(void* const* d_in, const int* in_sizes, int n_in,
                              void* d_out, int out_size)
{
    const float* x      = (const float*)d_in[0];
    const float* W_attn = (const float*)d_in[1];
    const float* b_attn = (const float*)d_in[2];
    const float* W_proj = (const float*)d_in[3];
    const float* b_proj = (const float*)d_in[4];
    float* out = (float*)d_out;

    __nv_bfloat16 *xh, *xl, *wah, *wal, *wph, *wpl;
    __nv_bfloat16 *qh, *ql, *kh, *kl, *vth, *vtl, *oh, *ol;
    cudaGetSymbolAddress((void**)&xh, g_xh);   cudaGetSymbolAddress((void**)&xl, g_xl);
    cudaGetSymbolAddress((void**)&wah, g_wah); cudaGetSymbolAddress((void**)&wal, g_wal);
    cudaGetSymbolAddress((void**)&wph, g_wph); cudaGetSymbolAddress((void**)&wpl, g_wpl);
    cudaGetSymbolAddress((void**)&qh, g_qh);   cudaGetSymbolAddress((void**)&ql, g_ql);
    cudaGetSymbolAddress((void**)&kh, g_kh);   cudaGetSymbolAddress((void**)&kl, g_kl);
    cudaGetSymbolAddress((void**)&vth, g_vth); cudaGetSymbolAddress((void**)&vtl, g_vtl);
    cudaGetSymbolAddress((void**)&oh, g_oh);   cudaGetSymbolAddress((void**)&ol, g_ol);

    cudaFuncSetAttribute(gemm_mma<0>, cudaFuncAttributeMaxDynamicSharedMemorySize, GSMEM);
    cudaFuncSetAttribute(gemm_mma<1>, cudaFuncAttributeMaxDynamicSharedMemorySize, GSMEM);
    cudaFuncSetAttribute(attn_mma,    cudaFuncAttributeMaxDynamicSharedMemorySize, ASMEM);

    // 0) fp32 -> bf16 hi/lo conversions
    conv_kernel<<<Mrows*Ee/1024, 256>>>(x, xh, xl, Mrows*Ee);
    conv_kernel<<<3*Ee*Ee/1024, 256>>>(W_attn, wah, wal, 3*Ee*Ee);
    conv_kernel<<<Ee*Ee/1024, 256>>>(W_proj, wph, wpl, Ee*Ee);

    // 1) QKV projection -> bf16 q(scaled)/k hi,lo + V^T hi,lo
    gemm_mma<1><<<dim3(3*Ee/128, Mrows/128), 256, GSMEM>>>(
        xh, xl, wah, wal, b_attn, nullptr,
        qh, ql, kh, kl, vth, vtl, Mrows, 3*Ee, Ee);

    // 2) Causal flash attention -> merged-head bf16 hi/lo
    attn_mma<<<dim3(Sq/128, Bb*Hh), 256, ASMEM>>>(qh, ql, kh, kl, vth, vtl, oh, ol);

    // 3) Output projection -> fp32 out
    gemm_mma<0><<<dim3(Ee/128, Mrows/128), 256, GSMEM>>>(
        oh, ol, wph, wpl, b_proj, out,
        nullptr, nullptr, nullptr, nullptr, nullptr, nullptr, Mrows, Ee, Ee);
}

// round 6
// speedup vs baseline: 3.3516x; 1.0027x over previous
#include <cuda_runtime.h>
#include <cuda_bf16.h>
#include <cstdint>

// Problem constants
#define Bb 2
#define Sq 2048
#define Ee 1024
#define Hh 16
#define Dd 64
#define Mrows (Bb*Sq)   // 4096

// Scratch (device globals: allocation-free, graph-capturable)
__device__ __nv_bfloat16 g_xh[(size_t)Mrows*Ee],  g_xl[(size_t)Mrows*Ee];
__device__ __nv_bfloat16 g_wah[(size_t)3*Ee*Ee],  g_wal[(size_t)3*Ee*Ee];
__device__ __nv_bfloat16 g_wph[(size_t)Ee*Ee],    g_wpl[(size_t)Ee*Ee];
__device__ __nv_bfloat16 g_qh[(size_t)Bb*Hh*Sq*Dd], g_ql[(size_t)Bb*Hh*Sq*Dd];
__device__ __nv_bfloat16 g_kh[(size_t)Bb*Hh*Sq*Dd], g_kl[(size_t)Bb*Hh*Sq*Dd];
__device__ __nv_bfloat16 g_vth[(size_t)Bb*Hh*Dd*Sq], g_vtl[(size_t)Bb*Hh*Dd*Sq]; // [bh][d][s]
__device__ __nv_bfloat16 g_oh[(size_t)Mrows*Ee],  g_ol[(size_t)Mrows*Ee];

// ---------------------------------------------------------------------------
// helpers (all plain sm_80-era PTX: valid on compute_103 virtual arch)
// ---------------------------------------------------------------------------
__device__ __forceinline__ uint32_t smem_u32(const void* p) {
    uint32_t a;
    asm("{ .reg .u64 t; cvta.to.shared.u64 t, %1; cvt.u32.u64 %0, t; }"
        : "=r"(a) : "l"(p));
    return a;
}
#define CPA(dst, src) \
    asm volatile("cp.async.cg.shared.global [%0], [%1], 16;" :: "r"(dst), "l"(src))
#define CP_COMMIT() asm volatile("cp.async.commit_group;")
#define CP_WAIT1()  asm volatile("cp.async.wait_group 1;" ::: "memory")
#define CP_WAIT0()  asm volatile("cp.async.wait_group 0;" ::: "memory")

#define LDSM4(r, addr) \
    asm volatile("ldmatrix.sync.aligned.m8n8.x4.shared.b16 {%0,%1,%2,%3}, [%4];" \
        : "=r"((r)[0]), "=r"((r)[1]), "=r"((r)[2]), "=r"((r)[3]) : "r"(addr))

__device__ __forceinline__ void mma_bf16(float* c, const uint32_t* a,
                                         uint32_t b0, uint32_t b1) {
    asm volatile(
        "mma.sync.aligned.m16n8k16.row.col.f32.bf16.bf16.f32 "
        "{%0,%1,%2,%3}, {%4,%5,%6,%7}, {%8,%9}, {%0,%1,%2,%3};"
        : "+f"(c[0]), "+f"(c[1]), "+f"(c[2]), "+f"(c[3])
        : "r"(a[0]), "r"(a[1]), "r"(a[2]), "r"(a[3]), "r"(b0), "r"(b1));
}

__device__ __forceinline__ void hsplit(float v, __nv_bfloat16& h, __nv_bfloat16& l) {
    h = __float2bfloat16(v);
    l = __float2bfloat16(v - __bfloat162float(h));
}
__device__ __forceinline__ uint32_t pack2(__nv_bfloat16 lo, __nv_bfloat16 hi) {
    __nv_bfloat162 t(lo, hi);
    return *(uint32_t*)&t;
}

// ---------------------------------------------------------------------------
// fp32 -> (hi, lo) bf16 pair conversion
// ---------------------------------------------------------------------------
__global__ __launch_bounds__(256)
void conv_kernel(const float* __restrict__ src, __nv_bfloat16* __restrict__ hi,
                 __nv_bfloat16* __restrict__ lo, int n)
{
    int i = (blockIdx.x * 256 + threadIdx.x) * 4;
    if (i >= n) return;
    float4 v = *(const float4*)(src + i);
    __nv_bfloat16 h0, h1, h2, h3, l0, l1, l2, l3;
    hsplit(v.x, h0, l0); hsplit(v.y, h1, l1);
    hsplit(v.z, h2, l2); hsplit(v.w, h3, l3);
    ((__nv_bfloat162*)(hi + i))[0] = __nv_bfloat162(h0, h1);
    ((__nv_bfloat162*)(hi + i))[1] = __nv_bfloat162(h2, h3);
    ((__nv_bfloat162*)(lo + i))[0] = __nv_bfloat162(l0, l1);
    ((__nv_bfloat162*)(lo + i))[1] = __nv_bfloat162(l2, l3);
}

// ---------------------------------------------------------------------------
// GEMM via mma.sync bf16 pairs: C[M,N] = (Ah+Al)(Bh+Bl)^T + bias
// 128x128 CTA tile, 8 warps (warp tile 32x64), K-chunk 32, cp.async 2-stage,
// ldmatrix.x4 loads, 2 CTAs/SM, MMAs round-robined across 4 accumulators
// (dependency distance 4) to cover HMMA latency.
// ---------------------------------------------------------------------------
#define GST   40960
#define GSMEM (2*GST)

template<int SCATTER>
__global__ __launch_bounds__(256, 2)
void gemm_mma(const __nv_bfloat16* __restrict__ Ahg, const __nv_bfloat16* __restrict__ Alg,
              const __nv_bfloat16* __restrict__ Bhg, const __nv_bfloat16* __restrict__ Blg,
              const float* __restrict__ bias, float* __restrict__ C,
              __nv_bfloat16* __restrict__ Qh, __nv_bfloat16* __restrict__ Ql,
              __nv_bfloat16* __restrict__ Kh, __nv_bfloat16* __restrict__ Kl,
              __nv_bfloat16* __restrict__ Vth, __nv_bfloat16* __restrict__ Vtl,
              int M, int N, int K)
{
    extern __shared__ __align__(16) char smg[];
    uint32_t sb = smem_u32(smg);
    int tid = threadIdx.x;
    int lane = tid & 31, warp = tid >> 5;
    int wm = warp >> 1, wn = warp & 1;
    int g = lane >> 2, t2 = (lane & 3) * 2;
    int m0 = blockIdx.y * 128, n0 = blockIdx.x * 128;

    uint32_t aOff = (uint32_t)((wm * 32 + (lane & 15)) * 80 + ((lane >> 4) << 3) * 2);
    uint32_t bOff = (uint32_t)((wn * 64 + ((lane >> 4) << 3) + (lane & 7)) * 80 +
                               (((lane >> 3) & 1) << 3) * 2);

    const __nv_bfloat16* srcs[4] = {
        Ahg + (size_t)m0 * K, Alg + (size_t)m0 * K,
        Bhg + (size_t)n0 * K, Blg + (size_t)n0 * K };

    auto load_chunk = [&](int kt, int st) {
        uint32_t stb = sb + st * GST;
        #pragma unroll
        for (int b = 0; b < 4; b++) {
            const __nv_bfloat16* base = srcs[b] + kt;
            #pragma unroll
            for (int it = 0; it < 2; it++) {
                int idx = tid + it * 256;            // 0..511
                int r = idx >> 2, cg = idx & 3;      // 128 rows x 4 chunks(16B)
                CPA(stb + b * 10240 + r * 80 + cg * 16,
                    base + (size_t)r * K + cg * 8);
            }
        }
        CP_COMMIT();
    };

    float acc[2][8][4] = {};
    load_chunk(0, 0);
    int nch = K >> 5;
    for (int c = 0; c < nch; c++) {
        if (c + 1 < nch) { load_chunk((c + 1) * 32, (c + 1) & 1); CP_WAIT1(); }
        else             { CP_WAIT0(); }
        __syncthreads();
        uint32_t stb = sb + (c & 1) * GST;
        #pragma unroll
        for (int kk = 0; kk < 32; kk += 16) {
            uint32_t aH[2][4], aL[2][4];
            LDSM4(aH[0], stb + aOff + kk * 2);
            LDSM4(aH[1], stb + aOff + kk * 2 + 16 * 80);
            LDSM4(aL[0], stb + 10240 + aOff + kk * 2);
            LDSM4(aL[1], stb + 10240 + aOff + kk * 2 + 16 * 80);
            #pragma unroll
            for (int j2 = 0; j2 < 4; j2++) {
                uint32_t bhf[4], blf[4];
                LDSM4(bhf, stb + 20480 + bOff + j2 * 1280 + kk * 2);
                LDSM4(blf, stb + 30720 + bOff + j2 * 1280 + kk * 2);
                // round-robin across 4 independent accumulators (dep dist = 4)
                mma_bf16(acc[0][2*j2],   aH[0], bhf[0], bhf[1]);
                mma_bf16(acc[1][2*j2],   aH[1], bhf[0], bhf[1]);
                mma_bf16(acc[0][2*j2+1], aH[0], bhf[2], bhf[3]);
                mma_bf16(acc[1][2*j2+1], aH[1], bhf[2], bhf[3]);
                mma_bf16(acc[0][2*j2],   aH[0], blf[0], blf[1]);
                mma_bf16(acc[1][2*j2],   aH[1], blf[0], blf[1]);
                mma_bf16(acc[0][2*j2+1], aH[0], blf[2], blf[3]);
                mma_bf16(acc[1][2*j2+1], aH[1], blf[2], blf[3]);
                mma_bf16(acc[0][2*j2],   aL[0], bhf[0], bhf[1]);
                mma_bf16(acc[1][2*j2],   aL[1], bhf[0], bhf[1]);
                mma_bf16(acc[0][2*j2+1], aL[0], bhf[2], bhf[3]);
                mma_bf16(acc[1][2*j2+1], aL[1], bhf[2], bhf[3]);
            }
        }
        __syncthreads();
    }

    // epilogue
    #pragma unroll
    for (int i = 0; i < 2; i++) {
        #pragma unroll
        for (int e2 = 0; e2 < 2; e2++) {
            int m = m0 + wm * 32 + i * 16 + g + e2 * 8;
            #pragma unroll
            for (int j = 0; j < 8; j++) {
                int n = n0 + wn * 64 + j * 8 + t2;
                float v0 = acc[i][j][e2*2+0] + bias[n];
                float v1 = acc[i][j][e2*2+1] + bias[n+1];
                if (SCATTER == 0) {
                    *(float2*)(C + (size_t)m * N + n) = make_float2(v0, v1);
                } else {
                    int part = n >> 10, e = n & 1023, hh = e >> 6, d = e & 63;
                    int b = m >> 11, s = m & 2047;
                    int bh = b * Hh + hh;
                    if (part == 0) { v0 *= 0.125f; v1 *= 0.125f; }
                    __nv_bfloat16 h0, l0, h1, l1;
                    hsplit(v0, h0, l0); hsplit(v1, h1, l1);
                    if (part < 2) {
                        size_t i0 = ((size_t)bh * Sq + s) * Dd + d;
                        __nv_bfloat16* dh = (part == 0 ? Qh : Kh) + i0;
                        __nv_bfloat16* dl = (part == 0 ? Ql : Kl) + i0;
                        *(__nv_bfloat162*)dh = __nv_bfloat162(h0, h1);
                        *(__nv_bfloat162*)dl = __nv_bfloat162(l0, l1);
                    } else {
                        size_t i0 = ((size_t)bh * Dd + d) * Sq + s;
                        Vth[i0] = h0; Vth[i0 + Sq] = h1;
                        Vtl[i0] = l0; Vtl[i0 + Sq] = l1;
                    }
                }
            }
        }
    }
}

// ---------------------------------------------------------------------------
// Flash attention on mma.sync bf16 pairs + ldmatrix fragment loads.
// CTA: 128 q rows, 8 warps (16 q rows each). Key tiles of 64, cp.async 2-stage.
// QK/PV MMAs interleaved across 4 accumulators (j2 pairs) for dep distance 4.
// ---------------------------------------------------------------------------
#define AST0  36864
#define ASTG  36864
#define ASMEM (AST0 + 2*ASTG)   // 110592

__global__ __launch_bounds__(256, 2)
void attn_mma(const __nv_bfloat16* __restrict__ Qhg, const __nv_bfloat16* __restrict__ Qlg,
              const __nv_bfloat16* __restrict__ Khg, const __nv_bfloat16* __restrict__ Klg,
              const __nv_bfloat16* __restrict__ Vhg, const __nv_bfloat16* __restrict__ Vlg,
              __nv_bfloat16* __restrict__ Oh, __nv_bfloat16* __restrict__ Ol)
{
    extern __shared__ __align__(16) char sma[];
    uint32_t sb = smem_u32(sma);
    int tid = threadIdx.x, lane = tid & 31, w = tid >> 5;
    int g = lane >> 2, t2 = (lane & 3) * 2;
    int bh = blockIdx.y;
    int qt = gridDim.x - 1 - (int)blockIdx.x;   // heavy q-tiles first
    int q0 = qt * 128;

    uint32_t qOff = (uint32_t)((w * 16 + (lane & 15)) * 144 + ((lane >> 4) << 3) * 2);
    uint32_t kOff = (uint32_t)((((lane >> 4) << 3) + (lane & 7)) * 144 +
                               (((lane >> 3) & 1) << 3) * 2);

    const __nv_bfloat16* Khb = Khg + (size_t)bh * Sq * Dd;
    const __nv_bfloat16* Klb = Klg + (size_t)bh * Sq * Dd;
    const __nv_bfloat16* Vhb = Vhg + (size_t)bh * Dd * Sq;
    const __nv_bfloat16* Vlb = Vlg + (size_t)bh * Dd * Sq;

    // Q tiles -> smem (group 0)
    {
        const __nv_bfloat16* q0p = Qhg + ((size_t)bh * Sq + q0) * Dd;
        const __nv_bfloat16* q1p = Qlg + ((size_t)bh * Sq + q0) * Dd;
        #pragma unroll
        for (int it = 0; it < 4; it++) {
            int idx = tid + it * 256;           // 0..1023
            int r = idx >> 3, cg = idx & 7;     // 128 rows x 8 chunks
            CPA(sb + r * 144 + cg * 16,         q0p + (size_t)r * Dd + cg * 8);
            CPA(sb + 18432 + r * 144 + cg * 16, q1p + (size_t)r * Dd + cg * 8);
        }
        CP_COMMIT();
    }

    auto load_tile = [&](int t, int st) {
        uint32_t stb = sb + AST0 + st * ASTG;
        int k0 = t * 64;
        #pragma unroll
        for (int it = 0; it < 2; it++) {
            int idx = tid + it * 256;           // 0..511
            int r = idx >> 3, cg = idx & 7;     // 64 rows x 8 chunks
            CPA(stb +         r * 144 + cg * 16, Khb + (size_t)(k0 + r) * Dd + cg * 8);
            CPA(stb +  9216 + r * 144 + cg * 16, Klb + (size_t)(k0 + r) * Dd + cg * 8);
            CPA(stb + 18432 + r * 144 + cg * 16, Vhb + (size_t)r * Sq + k0 + cg * 8);
            CPA(stb + 27648 + r * 144 + cg * 16, Vlb + (size_t)r * Sq + k0 + cg * 8);
        }
        CP_COMMIT();
    };

    int T = 2 * qt + 2;
    load_tile(0, 0);

    float o[8][4] = {};
    float m0r = -1e30f, m1r = -1e30f, l0 = 0.f, l1 = 0.f;
    int qwmin = q0 + w * 16;

    for (int t = 0; t < T; t++) {
        if (t + 1 < T) { load_tile(t + 1, (t + 1) & 1); CP_WAIT1(); }
        else           { CP_WAIT0(); }
        __syncthreads();

        if (64 * t <= qwmin + 15) {
            uint32_t kb = sb + AST0 + (t & 1) * ASTG;

            // ---- QK ----
            float s[8][4] = {};
            #pragma unroll
            for (int ks = 0; ks < 4; ks++) {
                int kk = ks * 16;
                uint32_t aH[4], aL[4];
                LDSM4(aH, sb + qOff + kk * 2);
                LDSM4(aL, sb + 18432 + qOff + kk * 2);
                #pragma unroll
                for (int jp = 0; jp < 2; jp++) {   // j2 pairs -> 4 indep accs
                    int j2a = 2 * jp, j2b = 2 * jp + 1;
                    uint32_t b0h[4], b0l[4], b1h[4], b1l[4];
                    LDSM4(b0h, kb +        kOff + j2a * 2304 + kk * 2);
                    LDSM4(b0l, kb + 9216 + kOff + j2a * 2304 + kk * 2);
                    LDSM4(b1h, kb +        kOff + j2b * 2304 + kk * 2);
                    LDSM4(b1l, kb + 9216 + kOff + j2b * 2304 + kk * 2);
                    mma_bf16(s[2*j2a],   aH, b0h[0], b0h[1]);
                    mma_bf16(s[2*j2a+1], aH, b0h[2], b0h[3]);
                    mma_bf16(s[2*j2b],   aH, b1h[0], b1h[1]);
                    mma_bf16(s[2*j2b+1], aH, b1h[2], b1h[3]);
                    mma_bf16(s[2*j2a],   aH, b0l[0], b0l[1]);
                    mma_bf16(s[2*j2a+1], aH, b0l[2], b0l[3]);
                    mma_bf16(s[2*j2b],   aH, b1l[0], b1l[1]);
                    mma_bf16(s[2*j2b+1], aH, b1l[2], b1l[3]);
                    mma_bf16(s[2*j2a],   aL, b0h[0], b0h[1]);
                    mma_bf16(s[2*j2a+1], aL, b0h[2], b0h[3]);
                    mma_bf16(s[2*j2b],   aL, b1h[0], b1h[1]);
                    mma_bf16(s[2*j2b+1], aL, b1h[2], b1h[3]);
                }
            }

            // ---- causal mask ----
            if (64 * t + 63 > qwmin) {
                int qr0 = qwmin + g, qr1 = qwmin + g + 8;
                #pragma unroll
                for (int j = 0; j < 8; j++) {
                    int kbi = 64 * t + j * 8 + t2;
                    if (kbi     > qr0) s[j][0] = -1e30f;
                    if (kbi + 1 > qr0) s[j][1] = -1e30f;
                    if (kbi     > qr1) s[j][2] = -1e30f;
                    if (kbi + 1 > qr1) s[j][3] = -1e30f;
                }
            }

            // ---- online softmax ----
            float mx0 = -1e30f, mx1 = -1e30f;
            #pragma unroll
            for (int j = 0; j < 8; j++) {
                mx0 = fmaxf(mx0, fmaxf(s[j][0], s[j][1]));
                mx1 = fmaxf(mx1, fmaxf(s[j][2], s[j][3]));
            }
            #pragma unroll
            for (int off = 1; off < 4; off <<= 1) {
                mx0 = fmaxf(mx0, __shfl_xor_sync(0xffffffffu, mx0, off, 4));
                mx1 = fmaxf(mx1, __shfl_xor_sync(0xffffffffu, mx1, off, 4));
            }
            mx0 = fmaxf(mx0, m0r);
            mx1 = fmaxf(mx1, m1r);
            float al0 = __expf(m0r - mx0), al1 = __expf(m1r - mx1);
            m0r = mx0; m1r = mx1;
            l0 *= al0;  l1 *= al1;
            #pragma unroll
            for (int j = 0; j < 8; j++) {
                s[j][0] = __expf(s[j][0] - mx0);
                s[j][1] = __expf(s[j][1] - mx0);
                s[j][2] = __expf(s[j][2] - mx1);
                s[j][3] = __expf(s[j][3] - mx1);
                l0 += s[j][0] + s[j][1];
                l1 += s[j][2] + s[j][3];
                o[j][0] *= al0; o[j][1] *= al0;
                o[j][2] *= al1; o[j][3] *= al1;
            }

            // ---- PV ----
            #pragma unroll
            for (int ks = 0; ks < 4; ks++) {
                int j0 = 2 * ks, j1 = 2 * ks + 1;
                __nv_bfloat16 h, l, h2, l2;
                uint32_t pH[4], pL[4];
                hsplit(s[j0][0], h, l); hsplit(s[j0][1], h2, l2);
                pH[0] = pack2(h, h2); pL[0] = pack2(l, l2);
                hsplit(s[j0][2], h, l); hsplit(s[j0][3], h2, l2);
                pH[1] = pack2(h, h2); pL[1] = pack2(l, l2);
                hsplit(s[j1][0], h, l); hsplit(s[j1][1], h2, l2);
                pH[2] = pack2(h, h2); pL[2] = pack2(l, l2);
                hsplit(s[j1][2], h, l); hsplit(s[j1][3], h2, l2);
                pH[3] = pack2(h, h2); pL[3] = pack2(l, l2);
                #pragma unroll
                for (int jp = 0; jp < 2; jp++) {   // j2 pairs -> 4 indep accs
                    int j2a = 2 * jp, j2b = 2 * jp + 1;
                    uint32_t v0h[4], v0l[4], v1h[4], v1l[4];
                    LDSM4(v0h, kb + 18432 + kOff + j2a * 2304 + ks * 32);
                    LDSM4(v0l, kb + 27648 + kOff + j2a * 2304 + ks * 32);
                    LDSM4(v1h, kb + 18432 + kOff + j2b * 2304 + ks * 32);
                    LDSM4(v1l, kb + 27648 + kOff + j2b * 2304 + ks * 32);
                    mma_bf16(o[2*j2a],   pH, v0h[0], v0h[1]);
                    mma_bf16(o[2*j2a+1], pH, v0h[2], v0h[3]);
                    mma_bf16(o[2*j2b],   pH, v1h[0], v1h[1]);
                    mma_bf16(o[2*j2b+1], pH, v1h[2], v1h[3]);
                    mma_bf16(o[2*j2a],   pH, v0l[0], v0l[1]);
                    mma_bf16(o[2*j2a+1], pH, v0l[2], v0l[3]);
                    mma_bf16(o[2*j2b],   pH, v1l[0], v1l[1]);
                    mma_bf16(o[2*j2b+1], pH, v1l[2], v1l[3]);
                    mma_bf16(o[2*j2a],   pL, v0h[0], v0h[1]);
                    mma_bf16(o[2*j2a+1], pL, v0h[2], v0h[3]);
                    mma_bf16(o[2*j2b],   pL, v1h[0], v1h[1]);
                    mma_bf16(o[2*j2b+1], pL, v1h[2], v1h[3]);
                }
            }
        }
        __syncthreads();
    }

    // ---- finalize ----
    #pragma unroll
    for (int off = 1; off < 4; off <<= 1) {
        l0 += __shfl_xor_sync(0xffffffffu, l0, off, 4);
        l1 += __shfl_xor_sync(0xffffffffu, l1, off, 4);
    }
    float inv0 = 1.f / l0, inv1 = 1.f / l1;
    int b = bh >> 4, hh = bh & 15;
    int r0 = q0 + w * 16 + g, r1 = r0 + 8;
    #pragma unroll
    for (int j = 0; j < 8; j++) {
        int d = j * 8 + t2;
        __nv_bfloat16 h0, l0b, h1, l1b;
        size_t i0 = ((size_t)(b * Sq + r0)) * Ee + hh * Dd + d;
        hsplit(o[j][0] * inv0, h0, l0b); hsplit(o[j][1] * inv0, h1, l1b);
        *(__nv_bfloat162*)(Oh + i0) = __nv_bfloat162(h0, h1);
        *(__nv_bfloat162*)(Ol + i0) = __nv_bfloat162(l0b, l1b);
        size_t i1 = ((size_t)(b * Sq + r1)) * Ee + hh * Dd + d;
        hsplit(o[j][2] * inv1, h0, l0b); hsplit(o[j][3] * inv1, h1, l1b);
        *(__nv_bfloat162*)(Oh + i1) = __nv_bfloat162(h0, h1);
        *(__nv_bfloat162*)(Ol + i1) = __nv_bfloat162(l0b, l1b);
    }
}

// ---------------------------------------------------------------------------
extern "C" void kernel_launch(void* const* d_in, const int* in_sizes, int n_in,
                              void* d_out, int out_size)
{
    const float* x      = (const float*)d_in[0];
    const float* W_attn = (const float*)d_in[1];
    const float* b_attn = (const float*)d_in[2];
    const float* W_proj = (const float*)d_in[3];
    const float* b_proj = (const float*)d_in[4];
    float* out = (float*)d_out;

    __nv_bfloat16 *xh, *xl, *wah, *wal, *wph, *wpl;
    __nv_bfloat16 *qh, *ql, *kh, *kl, *vth, *vtl, *oh, *ol;
    cudaGetSymbolAddress((void**)&xh, g_xh);   cudaGetSymbolAddress((void**)&xl, g_xl);
    cudaGetSymbolAddress((void**)&wah, g_wah); cudaGetSymbolAddress((void**)&wal, g_wal);
    cudaGetSymbolAddress((void**)&wph, g_wph); cudaGetSymbolAddress((void**)&wpl, g_wpl);
    cudaGetSymbolAddress((void**)&qh, g_qh);   cudaGetSymbolAddress((void**)&ql, g_ql);
    cudaGetSymbolAddress((void**)&kh, g_kh);   cudaGetSymbolAddress((void**)&kl, g_kl);
    cudaGetSymbolAddress((void**)&vth, g_vth); cudaGetSymbolAddress((void**)&vtl, g_vtl);
    cudaGetSymbolAddress((void**)&oh, g_oh);   cudaGetSymbolAddress((void**)&ol, g_ol);

    cudaFuncSetAttribute(gemm_mma<0>, cudaFuncAttributeMaxDynamicSharedMemorySize, GSMEM);
    cudaFuncSetAttribute(gemm_mma<1>, cudaFuncAttributeMaxDynamicSharedMemorySize, GSMEM);
    cudaFuncSetAttribute(attn_mma,    cudaFuncAttributeMaxDynamicSharedMemorySize, ASMEM);

    // 0) fp32 -> bf16 hi/lo conversions
    conv_kernel<<<Mrows*Ee/1024, 256>>>(x, xh, xl, Mrows*Ee);
    conv_kernel<<<3*Ee*Ee/1024, 256>>>(W_attn, wah, wal, 3*Ee*Ee);
    conv_kernel<<<Ee*Ee/1024, 256>>>(W_proj, wph, wpl, Ee*Ee);

    // 1) QKV projection -> bf16 q(scaled)/k hi,lo + V^T hi,lo
    gemm_mma<1><<<dim3(3*Ee/128, Mrows/128), 256, GSMEM>>>(
        xh, xl, wah, wal, b_attn, nullptr,
        qh, ql, kh, kl, vth, vtl, Mrows, 3*Ee, Ee);

    // 2) Causal flash attention -> merged-head bf16 hi/lo
    attn_mma<<<dim3(Sq/128, Bb*Hh), 256, ASMEM>>>(qh, ql, kh, kl, vth, vtl, oh, ol);

    // 3) Output projection -> fp32 out
    gemm_mma<0><<<dim3(Ee/128, Mrows/128), 256, GSMEM>>>(
        oh, ol, wph, wpl, b_proj, out,
        nullptr, nullptr, nullptr, nullptr, nullptr, nullptr, Mrows, Ee, Ee);
}

// round 7
// speedup vs baseline: 4.6222x; 1.3791x over previous
#include <cuda_runtime.h>
#include <cuda_fp16.h>
#include <cstdint>

// Problem constants
#define Bb 2
#define Sq 2048
#define Ee 1024
#define Hh 16
#define Dd 64
#define Mrows (Bb*Sq)   // 4096

// Scratch (device globals: allocation-free, graph-capturable)
__device__ __half g_xh[(size_t)Mrows*Ee];                                  // x single
__device__ __half g_wah[(size_t)3*Ee*Ee],  g_wal[(size_t)3*Ee*Ee];         // W_attn pair
__device__ __half g_wph[(size_t)Ee*Ee],    g_wpl[(size_t)Ee*Ee];           // W_proj pair
__device__ __half g_qh[(size_t)Bb*Hh*Sq*Dd];                               // q single (pre-scaled)
__device__ __half g_kh[(size_t)Bb*Hh*Sq*Dd], g_kl[(size_t)Bb*Hh*Sq*Dd];    // k pair
__device__ __half g_vth[(size_t)Bb*Hh*Dd*Sq], g_vtl[(size_t)Bb*Hh*Dd*Sq];  // V^T pair [bh][d][s]
__device__ __half g_oh[(size_t)Mrows*Ee];                                  // attn out single

// ---------------------------------------------------------------------------
// helpers (all plain sm_80-era PTX: valid on compute_103 virtual arch)
// ---------------------------------------------------------------------------
__device__ __forceinline__ uint32_t smem_u32(const void* p) {
    uint32_t a;
    asm("{ .reg .u64 t; cvta.to.shared.u64 t, %1; cvt.u32.u64 %0, t; }"
        : "=r"(a) : "l"(p));
    return a;
}
#define CPA(dst, src) \
    asm volatile("cp.async.cg.shared.global [%0], [%1], 16;" :: "r"(dst), "l"(src))
#define CP_COMMIT() asm volatile("cp.async.commit_group;")
#define CP_WAIT1()  asm volatile("cp.async.wait_group 1;" ::: "memory")
#define CP_WAIT0()  asm volatile("cp.async.wait_group 0;" ::: "memory")

#define LDSM4(r, addr) \
    asm volatile("ldmatrix.sync.aligned.m8n8.x4.shared.b16 {%0,%1,%2,%3}, [%4];" \
        : "=r"((r)[0]), "=r"((r)[1]), "=r"((r)[2]), "=r"((r)[3]) : "r"(addr))

__device__ __forceinline__ void mma_f16(float* c, const uint32_t* a,
                                        uint32_t b0, uint32_t b1) {
    asm volatile(
        "mma.sync.aligned.m16n8k16.row.col.f32.f16.f16.f32 "
        "{%0,%1,%2,%3}, {%4,%5,%6,%7}, {%8,%9}, {%0,%1,%2,%3};"
        : "+f"(c[0]), "+f"(c[1]), "+f"(c[2]), "+f"(c[3])
        : "r"(a[0]), "r"(a[1]), "r"(a[2]), "r"(a[3]), "r"(b0), "r"(b1));
}

__device__ __forceinline__ void hsplit(float v, __half& h, __half& l) {
    h = __float2half(v);
    l = __float2half(v - __half2float(h));
}
__device__ __forceinline__ uint32_t pack2(__half lo, __half hi) {
    __half2 t(lo, hi);
    return *(uint32_t*)&t;
}

// ---------------------------------------------------------------------------
// fp32 -> fp16 conversions (pair / single)
// ---------------------------------------------------------------------------
__global__ __launch_bounds__(256)
void conv_pair(const float* __restrict__ src, __half* __restrict__ hi,
               __half* __restrict__ lo, int n)
{
    int i = (blockIdx.x * 256 + threadIdx.x) * 4;
    if (i >= n) return;
    float4 v = *(const float4*)(src + i);
    __half h0, h1, h2, h3, l0, l1, l2, l3;
    hsplit(v.x, h0, l0); hsplit(v.y, h1, l1);
    hsplit(v.z, h2, l2); hsplit(v.w, h3, l3);
    ((__half2*)(hi + i))[0] = __half2(h0, h1);
    ((__half2*)(hi + i))[1] = __half2(h2, h3);
    ((__half2*)(lo + i))[0] = __half2(l0, l1);
    ((__half2*)(lo + i))[1] = __half2(l2, l3);
}

__global__ __launch_bounds__(256)
void conv_single(const float* __restrict__ src, __half* __restrict__ hi, int n)
{
    int i = (blockIdx.x * 256 + threadIdx.x) * 4;
    if (i >= n) return;
    float4 v = *(const float4*)(src + i);
    ((__half2*)(hi + i))[0] = __half2(__float2half(v.x), __float2half(v.y));
    ((__half2*)(hi + i))[1] = __half2(__float2half(v.z), __float2half(v.w));
}

// ---------------------------------------------------------------------------
// GEMM: C[M,N] = A_f16[M,K] @ (Bh+Bl)[N,K]^T + bias  (2 MMA products)
// 128x128 CTA tile, 8 warps (warp tile 32x64), K-chunk 32, cp.async 2-stage,
// ldmatrix.x4, 2 CTAs/SM.
// smem stage: A, Bh, Bl each [128][40] half (10240B) -> 30720B/stage.
// ---------------------------------------------------------------------------
#define GST   30720
#define GSMEM (2*GST)

template<int SCATTER>
__global__ __launch_bounds__(256, 2)
void gemm_mma(const __half* __restrict__ Ag,
              const __half* __restrict__ Bhg, const __half* __restrict__ Blg,
              const float* __restrict__ bias, float* __restrict__ C,
              __half* __restrict__ Qh,
              __half* __restrict__ Kh, __half* __restrict__ Kl,
              __half* __restrict__ Vth, __half* __restrict__ Vtl,
              int M, int N, int K)
{
    extern __shared__ __align__(16) char smg[];
    uint32_t sb = smem_u32(smg);
    int tid = threadIdx.x;
    int lane = tid & 31, warp = tid >> 5;
    int wm = warp >> 1, wn = warp & 1;
    int g = lane >> 2, t2 = (lane & 3) * 2;
    int m0 = blockIdx.y * 128, n0 = blockIdx.x * 128;

    uint32_t aOff = (uint32_t)((wm * 32 + (lane & 15)) * 80 + ((lane >> 4) << 3) * 2);
    uint32_t bOff = (uint32_t)((wn * 64 + ((lane >> 4) << 3) + (lane & 7)) * 80 +
                               (((lane >> 3) & 1) << 3) * 2);

    const __half* srcs[3] = {
        Ag + (size_t)m0 * K, Bhg + (size_t)n0 * K, Blg + (size_t)n0 * K };

    auto load_chunk = [&](int kt, int st) {
        uint32_t stb = sb + st * GST;
        #pragma unroll
        for (int b = 0; b < 3; b++) {
            const __half* base = srcs[b] + kt;
            #pragma unroll
            for (int it = 0; it < 2; it++) {
                int idx = tid + it * 256;            // 0..511
                int r = idx >> 2, cg = idx & 3;      // 128 rows x 4 chunks(16B)
                CPA(stb + b * 10240 + r * 80 + cg * 16,
                    base + (size_t)r * K + cg * 8);
            }
        }
        CP_COMMIT();
    };

    float acc[2][8][4] = {};
    load_chunk(0, 0);
    int nch = K >> 5;
    for (int c = 0; c < nch; c++) {
        if (c + 1 < nch) { load_chunk((c + 1) * 32, (c + 1) & 1); CP_WAIT1(); }
        else             { CP_WAIT0(); }
        __syncthreads();
        uint32_t stb = sb + (c & 1) * GST;
        #pragma unroll
        for (int kk = 0; kk < 32; kk += 16) {
            uint32_t aF[2][4];
            LDSM4(aF[0], stb + aOff + kk * 2);
            LDSM4(aF[1], stb + aOff + kk * 2 + 16 * 80);
            #pragma unroll
            for (int j2 = 0; j2 < 4; j2++) {
                uint32_t bhf[4], blf[4];
                LDSM4(bhf, stb + 10240 + bOff + j2 * 1280 + kk * 2);
                LDSM4(blf, stb + 20480 + bOff + j2 * 1280 + kk * 2);
                mma_f16(acc[0][2*j2],   aF[0], bhf[0], bhf[1]);
                mma_f16(acc[1][2*j2],   aF[1], bhf[0], bhf[1]);
                mma_f16(acc[0][2*j2+1], aF[0], bhf[2], bhf[3]);
                mma_f16(acc[1][2*j2+1], aF[1], bhf[2], bhf[3]);
                mma_f16(acc[0][2*j2],   aF[0], blf[0], blf[1]);
                mma_f16(acc[1][2*j2],   aF[1], blf[0], blf[1]);
                mma_f16(acc[0][2*j2+1], aF[0], blf[2], blf[3]);
                mma_f16(acc[1][2*j2+1], aF[1], blf[2], blf[3]);
            }
        }
        __syncthreads();
    }

    // epilogue
    #pragma unroll
    for (int i = 0; i < 2; i++) {
        #pragma unroll
        for (int e2 = 0; e2 < 2; e2++) {
            int m = m0 + wm * 32 + i * 16 + g + e2 * 8;
            #pragma unroll
            for (int j = 0; j < 8; j++) {
                int n = n0 + wn * 64 + j * 8 + t2;
                float v0 = acc[i][j][e2*2+0] + bias[n];
                float v1 = acc[i][j][e2*2+1] + bias[n+1];
                if (SCATTER == 0) {
                    *(float2*)(C + (size_t)m * N + n) = make_float2(v0, v1);
                } else {
                    int part = n >> 10, e = n & 1023, hh = e >> 6, d = e & 63;
                    int b = m >> 11, s = m & 2047;
                    int bh = b * Hh + hh;
                    if (part == 0) {
                        // q single, pre-scaled
                        size_t i0 = ((size_t)bh * Sq + s) * Dd + d;
                        *(__half2*)(Qh + i0) =
                            __half2(__float2half(v0 * 0.125f), __float2half(v1 * 0.125f));
                    } else if (part == 1) {
                        __half h0, l0, h1, l1;
                        hsplit(v0, h0, l0); hsplit(v1, h1, l1);
                        size_t i0 = ((size_t)bh * Sq + s) * Dd + d;
                        *(__half2*)(Kh + i0) = __half2(h0, h1);
                        *(__half2*)(Kl + i0) = __half2(l0, l1);
                    } else {
                        __half h0, l0, h1, l1;
                        hsplit(v0, h0, l0); hsplit(v1, h1, l1);
                        size_t i0 = ((size_t)bh * Dd + d) * Sq + s;
                        Vth[i0] = h0; Vth[i0 + Sq] = h1;
                        Vtl[i0] = l0; Vtl[i0 + Sq] = l1;
                    }
                }
            }
        }
    }
}

// ---------------------------------------------------------------------------
// Flash attention, fp16 2-product: QK = Q*(Kh+Kl), PV = P*(Vh+Vl).
// CTA: 128 q rows, 8 warps (16 q rows each). Key tiles of 64, cp.async 2-stage.
// smem: Q [128][72] single; per stage Kh,Kl,Vth,Vtl [64][72].
// ---------------------------------------------------------------------------
#define AST0  18432
#define ASTG  36864
#define ASMEM (AST0 + 2*ASTG)   // 92160

__global__ __launch_bounds__(256, 2)
void attn_mma(const __half* __restrict__ Qg,
              const __half* __restrict__ Khg, const __half* __restrict__ Klg,
              const __half* __restrict__ Vhg, const __half* __restrict__ Vlg,
              __half* __restrict__ Oh)
{
    extern __shared__ __align__(16) char sma[];
    uint32_t sb = smem_u32(sma);
    int tid = threadIdx.x, lane = tid & 31, w = tid >> 5;
    int g = lane >> 2, t2 = (lane & 3) * 2;
    int bh = blockIdx.y;
    int qt = gridDim.x - 1 - (int)blockIdx.x;   // heavy q-tiles first
    int q0 = qt * 128;

    uint32_t qOff = (uint32_t)((w * 16 + (lane & 15)) * 144 + ((lane >> 4) << 3) * 2);
    uint32_t kOff = (uint32_t)((((lane >> 4) << 3) + (lane & 7)) * 144 +
                               (((lane >> 3) & 1) << 3) * 2);

    const __half* Khb = Khg + (size_t)bh * Sq * Dd;
    const __half* Klb = Klg + (size_t)bh * Sq * Dd;
    const __half* Vhb = Vhg + (size_t)bh * Dd * Sq;
    const __half* Vlb = Vlg + (size_t)bh * Dd * Sq;

    // Q tile -> smem (group 0)
    {
        const __half* qp = Qg + ((size_t)bh * Sq + q0) * Dd;
        #pragma unroll
        for (int it = 0; it < 4; it++) {
            int idx = tid + it * 256;           // 0..1023
            int r = idx >> 3, cg = idx & 7;     // 128 rows x 8 chunks
            CPA(sb + r * 144 + cg * 16, qp + (size_t)r * Dd + cg * 8);
        }
        CP_COMMIT();
    }

    auto load_tile = [&](int t, int st) {
        uint32_t stb = sb + AST0 + st * ASTG;
        int k0 = t * 64;
        #pragma unroll
        for (int it = 0; it < 2; it++) {
            int idx = tid + it * 256;           // 0..511
            int r = idx >> 3, cg = idx & 7;     // 64 rows x 8 chunks
            CPA(stb +         r * 144 + cg * 16, Khb + (size_t)(k0 + r) * Dd + cg * 8);
            CPA(stb +  9216 + r * 144 + cg * 16, Klb + (size_t)(k0 + r) * Dd + cg * 8);
            CPA(stb + 18432 + r * 144 + cg * 16, Vhb + (size_t)r * Sq + k0 + cg * 8);
            CPA(stb + 27648 + r * 144 + cg * 16, Vlb + (size_t)r * Sq + k0 + cg * 8);
        }
        CP_COMMIT();
    };

    int T = 2 * qt + 2;
    load_tile(0, 0);

    float o[8][4] = {};
    float m0r = -1e30f, m1r = -1e30f, l0 = 0.f, l1 = 0.f;
    int qwmin = q0 + w * 16;

    for (int t = 0; t < T; t++) {
        if (t + 1 < T) { load_tile(t + 1, (t + 1) & 1); CP_WAIT1(); }
        else           { CP_WAIT0(); }
        __syncthreads();

        if (64 * t <= qwmin + 15) {
            uint32_t kb = sb + AST0 + (t & 1) * ASTG;

            // ---- QK ----
            float s[8][4] = {};
            #pragma unroll
            for (int ks = 0; ks < 4; ks++) {
                int kk = ks * 16;
                uint32_t aF[4];
                LDSM4(aF, sb + qOff + kk * 2);
                #pragma unroll
                for (int jp = 0; jp < 2; jp++) {
                    int j2a = 2 * jp, j2b = 2 * jp + 1;
                    uint32_t b0h[4], b0l[4], b1h[4], b1l[4];
                    LDSM4(b0h, kb +        kOff + j2a * 2304 + kk * 2);
                    LDSM4(b0l, kb + 9216 + kOff + j2a * 2304 + kk * 2);
                    LDSM4(b1h, kb +        kOff + j2b * 2304 + kk * 2);
                    LDSM4(b1l, kb + 9216 + kOff + j2b * 2304 + kk * 2);
                    mma_f16(s[2*j2a],   aF, b0h[0], b0h[1]);
                    mma_f16(s[2*j2a+1], aF, b0h[2], b0h[3]);
                    mma_f16(s[2*j2b],   aF, b1h[0], b1h[1]);
                    mma_f16(s[2*j2b+1], aF, b1h[2], b1h[3]);
                    mma_f16(s[2*j2a],   aF, b0l[0], b0l[1]);
                    mma_f16(s[2*j2a+1], aF, b0l[2], b0l[3]);
                    mma_f16(s[2*j2b],   aF, b1l[0], b1l[1]);
                    mma_f16(s[2*j2b+1], aF, b1l[2], b1l[3]);
                }
            }

            // ---- causal mask ----
            if (64 * t + 63 > qwmin) {
                int qr0 = qwmin + g, qr1 = qwmin + g + 8;
                #pragma unroll
                for (int j = 0; j < 8; j++) {
                    int kbi = 64 * t + j * 8 + t2;
                    if (kbi     > qr0) s[j][0] = -1e30f;
                    if (kbi + 1 > qr0) s[j][1] = -1e30f;
                    if (kbi     > qr1) s[j][2] = -1e30f;
                    if (kbi + 1 > qr1) s[j][3] = -1e30f;
                }
            }

            // ---- online softmax ----
            float mx0 = -1e30f, mx1 = -1e30f;
            #pragma unroll
            for (int j = 0; j < 8; j++) {
                mx0 = fmaxf(mx0, fmaxf(s[j][0], s[j][1]));
                mx1 = fmaxf(mx1, fmaxf(s[j][2], s[j][3]));
            }
            #pragma unroll
            for (int off = 1; off < 4; off <<= 1) {
                mx0 = fmaxf(mx0, __shfl_xor_sync(0xffffffffu, mx0, off, 4));
                mx1 = fmaxf(mx1, __shfl_xor_sync(0xffffffffu, mx1, off, 4));
            }
            mx0 = fmaxf(mx0, m0r);
            mx1 = fmaxf(mx1, m1r);
            float al0 = __expf(m0r - mx0), al1 = __expf(m1r - mx1);
            m0r = mx0; m1r = mx1;
            l0 *= al0;  l1 *= al1;
            #pragma unroll
            for (int j = 0; j < 8; j++) {
                s[j][0] = __expf(s[j][0] - mx0);
                s[j][1] = __expf(s[j][1] - mx0);
                s[j][2] = __expf(s[j][2] - mx1);
                s[j][3] = __expf(s[j][3] - mx1);
                l0 += s[j][0] + s[j][1];
                l1 += s[j][2] + s[j][3];
                o[j][0] *= al0; o[j][1] *= al0;
                o[j][2] *= al1; o[j][3] *= al1;
            }

            // ---- PV (P single fp16) ----
            #pragma unroll
            for (int ks = 0; ks < 4; ks++) {
                int j0 = 2 * ks, j1 = 2 * ks + 1;
                uint32_t pF[4];
                pF[0] = pack2(__float2half(s[j0][0]), __float2half(s[j0][1]));
                pF[1] = pack2(__float2half(s[j0][2]), __float2half(s[j0][3]));
                pF[2] = pack2(__float2half(s[j1][0]), __float2half(s[j1][1]));
                pF[3] = pack2(__float2half(s[j1][2]), __float2half(s[j1][3]));
                #pragma unroll
                for (int jp = 0; jp < 2; jp++) {
                    int j2a = 2 * jp, j2b = 2 * jp + 1;
                    uint32_t v0h[4], v0l[4], v1h[4], v1l[4];
                    LDSM4(v0h, kb + 18432 + kOff + j2a * 2304 + ks * 32);
                    LDSM4(v0l, kb + 27648 + kOff + j2a * 2304 + ks * 32);
                    LDSM4(v1h, kb + 18432 + kOff + j2b * 2304 + ks * 32);
                    LDSM4(v1l, kb + 27648 + kOff + j2b * 2304 + ks * 32);
                    mma_f16(o[2*j2a],   pF, v0h[0], v0h[1]);
                    mma_f16(o[2*j2a+1], pF, v0h[2], v0h[3]);
                    mma_f16(o[2*j2b],   pF, v1h[0], v1h[1]);
                    mma_f16(o[2*j2b+1], pF, v1h[2], v1h[3]);
                    mma_f16(o[2*j2a],   pF, v0l[0], v0l[1]);
                    mma_f16(o[2*j2a+1], pF, v0l[2], v0l[3]);
                    mma_f16(o[2*j2b],   pF, v1l[0], v1l[1]);
                    mma_f16(o[2*j2b+1], pF, v1l[2], v1l[3]);
                }
            }
        }
        __syncthreads();
    }

    // ---- finalize ----
    #pragma unroll
    for (int off = 1; off < 4; off <<= 1) {
        l0 += __shfl_xor_sync(0xffffffffu, l0, off, 4);
        l1 += __shfl_xor_sync(0xffffffffu, l1, off, 4);
    }
    float inv0 = 1.f / l0, inv1 = 1.f / l1;
    int b = bh >> 4, hh = bh & 15;
    int r0 = q0 + w * 16 + g, r1 = r0 + 8;
    #pragma unroll
    for (int j = 0; j < 8; j++) {
        int d = j * 8 + t2;
        size_t i0 = ((size_t)(b * Sq + r0)) * Ee + hh * Dd + d;
        *(__half2*)(Oh + i0) =
            __half2(__float2half(o[j][0] * inv0), __float2half(o[j][1] * inv0));
        size_t i1 = ((size_t)(b * Sq + r1)) * Ee + hh * Dd + d;
        *(__half2*)(Oh + i1) =
            __half2(__float2half(o[j][2] * inv1), __float2half(o[j][3] * inv1));
    }
}

// ---------------------------------------------------------------------------
extern "C" void kernel_launch(void* const* d_in, const int* in_sizes, int n_in,
                              void* d_out, int out_size)
{
    const float* x      = (const float*)d_in[0];
    const float* W_attn = (const float*)d_in[1];
    const float* b_attn = (const float*)d_in[2];
    const float* W_proj = (const float*)d_in[3];
    const float* b_proj = (const float*)d_in[4];
    float* out = (float*)d_out;

    __half *xh, *wah, *wal, *wph, *wpl;
    __half *qh, *kh, *kl, *vth, *vtl, *oh;
    cudaGetSymbolAddress((void**)&xh, g_xh);
    cudaGetSymbolAddress((void**)&wah, g_wah); cudaGetSymbolAddress((void**)&wal, g_wal);
    cudaGetSymbolAddress((void**)&wph, g_wph); cudaGetSymbolAddress((void**)&wpl, g_wpl);
    cudaGetSymbolAddress((void**)&qh, g_qh);
    cudaGetSymbolAddress((void**)&kh, g_kh);   cudaGetSymbolAddress((void**)&kl, g_kl);
    cudaGetSymbolAddress((void**)&vth, g_vth); cudaGetSymbolAddress((void**)&vtl, g_vtl);
    cudaGetSymbolAddress((void**)&oh, g_oh);

    cudaFuncSetAttribute(gemm_mma<0>, cudaFuncAttributeMaxDynamicSharedMemorySize, GSMEM);
    cudaFuncSetAttribute(gemm_mma<1>, cudaFuncAttributeMaxDynamicSharedMemorySize, GSMEM);
    cudaFuncSetAttribute(attn_mma,    cudaFuncAttributeMaxDynamicSharedMemorySize, ASMEM);

    // 0) fp32 -> fp16 conversions
    conv_single<<<Mrows*Ee/1024, 256>>>(x, xh, Mrows*Ee);
    conv_pair<<<3*Ee*Ee/1024, 256>>>(W_attn, wah, wal, 3*Ee*Ee);
    conv_pair<<<Ee*Ee/1024, 256>>>(W_proj, wph, wpl, Ee*Ee);

    // 1) QKV projection -> q single (scaled), k pair, V^T pair
    gemm_mma<1><<<dim3(3*Ee/128, Mrows/128), 256, GSMEM>>>(
        xh, wah, wal, b_attn, nullptr,
        qh, kh, kl, vth, vtl, Mrows, 3*Ee, Ee);

    // 2) Causal flash attention -> merged-head fp16 single
    attn_mma<<<dim3(Sq/128, Bb*Hh), 256, ASMEM>>>(qh, kh, kl, vth, vtl, oh);

    // 3) Output projection -> fp32 out
    gemm_mma<0><<<dim3(Ee/128, Mrows/128), 256, GSMEM>>>(
        oh, wph, wpl, b_proj, out,
        nullptr, nullptr, nullptr, nullptr, nullptr, Mrows, Ee, Ee);
}

// round 8
// speedup vs baseline: 7.2523x; 1.5690x over previous
#include <cuda_runtime.h>
#include <cuda_fp16.h>
#include <cstdint>

// Problem constants
#define Bb 2
#define Sq 2048
#define Ee 1024
#define Hh 16
#define Dd 64
#define Mrows (Bb*Sq)   // 4096

// Scratch (device globals: allocation-free, graph-capturable)
__device__ __half g_xh[(size_t)Mrows*Ee];                  // x fp16
__device__ __half g_wah[(size_t)3*Ee*Ee];                  // W_attn fp16
__device__ __half g_wph[(size_t)Ee*Ee];                    // W_proj fp16
__device__ __half g_qh[(size_t)Bb*Hh*Sq*Dd];               // q fp16 (pre-scaled)
__device__ __half g_kh[(size_t)Bb*Hh*Sq*Dd];               // k fp16
__device__ __half g_vth[(size_t)Bb*Hh*Dd*Sq];              // V^T fp16 [bh][d][s]
__device__ __half g_oh[(size_t)Mrows*Ee];                  // attn out fp16

// ---------------------------------------------------------------------------
// helpers (all plain sm_80-era PTX: valid on compute_103 virtual arch)
// ---------------------------------------------------------------------------
__device__ __forceinline__ uint32_t smem_u32(const void* p) {
    uint32_t a;
    asm("{ .reg .u64 t; cvta.to.shared.u64 t, %1; cvt.u32.u64 %0, t; }"
        : "=r"(a) : "l"(p));
    return a;
}
#define CPA(dst, src) \
    asm volatile("cp.async.cg.shared.global [%0], [%1], 16;" :: "r"(dst), "l"(src))
#define CP_COMMIT() asm volatile("cp.async.commit_group;")
#define CP_WAIT1()  asm volatile("cp.async.wait_group 1;" ::: "memory")
#define CP_WAIT0()  asm volatile("cp.async.wait_group 0;" ::: "memory")

#define LDSM4(r, addr) \
    asm volatile("ldmatrix.sync.aligned.m8n8.x4.shared.b16 {%0,%1,%2,%3}, [%4];" \
        : "=r"((r)[0]), "=r"((r)[1]), "=r"((r)[2]), "=r"((r)[3]) : "r"(addr))

__device__ __forceinline__ void mma_f16(float* c, const uint32_t* a,
                                        uint32_t b0, uint32_t b1) {
    asm volatile(
        "mma.sync.aligned.m16n8k16.row.col.f32.f16.f16.f32 "
        "{%0,%1,%2,%3}, {%4,%5,%6,%7}, {%8,%9}, {%0,%1,%2,%3};"
        : "+f"(c[0]), "+f"(c[1]), "+f"(c[2]), "+f"(c[3])
        : "r"(a[0]), "r"(a[1]), "r"(a[2]), "r"(a[3]), "r"(b0), "r"(b1));
}

__device__ __forceinline__ uint32_t pack2(__half lo, __half hi) {
    __half2 t(lo, hi);
    return *(uint32_t*)&t;
}

// ---------------------------------------------------------------------------
// fp32 -> fp16 conversion
// ---------------------------------------------------------------------------
__global__ __launch_bounds__(256)
void conv_single(const float* __restrict__ src, __half* __restrict__ hi, int n)
{
    int i = (blockIdx.x * 256 + threadIdx.x) * 4;
    if (i >= n) return;
    float4 v = *(const float4*)(src + i);
    ((__half2*)(hi + i))[0] = __half2(__float2half(v.x), __float2half(v.y));
    ((__half2*)(hi + i))[1] = __half2(__float2half(v.z), __float2half(v.w));
}

// ---------------------------------------------------------------------------
// GEMM: C[M,N] = A_f16[M,K] @ B_f16[N,K]^T + bias  (single fp16 product)
// 128x128 CTA tile, 8 warps (warp tile 32x64), K-chunk 32, cp.async 2-stage,
// ldmatrix.x4, 2 CTAs/SM.
// smem stage: A, B each [128][40] half (10240B) -> 20480B/stage.
// ---------------------------------------------------------------------------
#define GST   20480
#define GSMEM (2*GST)

template<int SCATTER>
__global__ __launch_bounds__(256, 2)
void gemm_mma(const __half* __restrict__ Ag, const __half* __restrict__ Bg,
              const float* __restrict__ bias, float* __restrict__ C,
              __half* __restrict__ Qh, __half* __restrict__ Kh,
              __half* __restrict__ Vth,
              int M, int N, int K)
{
    extern __shared__ __align__(16) char smg[];
    uint32_t sb = smem_u32(smg);
    int tid = threadIdx.x;
    int lane = tid & 31, warp = tid >> 5;
    int wm = warp >> 1, wn = warp & 1;
    int g = lane >> 2, t2 = (lane & 3) * 2;
    int m0 = blockIdx.y * 128, n0 = blockIdx.x * 128;

    uint32_t aOff = (uint32_t)((wm * 32 + (lane & 15)) * 80 + ((lane >> 4) << 3) * 2);
    uint32_t bOff = (uint32_t)((wn * 64 + ((lane >> 4) << 3) + (lane & 7)) * 80 +
                               (((lane >> 3) & 1) << 3) * 2);

    const __half* srcs[2] = { Ag + (size_t)m0 * K, Bg + (size_t)n0 * K };

    auto load_chunk = [&](int kt, int st) {
        uint32_t stb = sb + st * GST;
        #pragma unroll
        for (int b = 0; b < 2; b++) {
            const __half* base = srcs[b] + kt;
            #pragma unroll
            for (int it = 0; it < 2; it++) {
                int idx = tid + it * 256;            // 0..511
                int r = idx >> 2, cg = idx & 3;      // 128 rows x 4 chunks(16B)
                CPA(stb + b * 10240 + r * 80 + cg * 16,
                    base + (size_t)r * K + cg * 8);
            }
        }
        CP_COMMIT();
    };

    float acc[2][8][4] = {};
    load_chunk(0, 0);
    int nch = K >> 5;
    for (int c = 0; c < nch; c++) {
        if (c + 1 < nch) { load_chunk((c + 1) * 32, (c + 1) & 1); CP_WAIT1(); }
        else             { CP_WAIT0(); }
        __syncthreads();
        uint32_t stb = sb + (c & 1) * GST;
        #pragma unroll
        for (int kk = 0; kk < 32; kk += 16) {
            uint32_t aF[2][4];
            LDSM4(aF[0], stb + aOff + kk * 2);
            LDSM4(aF[1], stb + aOff + kk * 2 + 16 * 80);
            #pragma unroll
            for (int j2 = 0; j2 < 4; j2++) {
                uint32_t bf[4];
                LDSM4(bf, stb + 10240 + bOff + j2 * 1280 + kk * 2);
                mma_f16(acc[0][2*j2],   aF[0], bf[0], bf[1]);
                mma_f16(acc[1][2*j2],   aF[1], bf[0], bf[1]);
                mma_f16(acc[0][2*j2+1], aF[0], bf[2], bf[3]);
                mma_f16(acc[1][2*j2+1], aF[1], bf[2], bf[3]);
            }
        }
        __syncthreads();
    }

    // epilogue
    #pragma unroll
    for (int i = 0; i < 2; i++) {
        #pragma unroll
        for (int e2 = 0; e2 < 2; e2++) {
            int m = m0 + wm * 32 + i * 16 + g + e2 * 8;
            #pragma unroll
            for (int j = 0; j < 8; j++) {
                int n = n0 + wn * 64 + j * 8 + t2;
                float v0 = acc[i][j][e2*2+0] + bias[n];
                float v1 = acc[i][j][e2*2+1] + bias[n+1];
                if (SCATTER == 0) {
                    *(float2*)(C + (size_t)m * N + n) = make_float2(v0, v1);
                } else {
                    int part = n >> 10, e = n & 1023, hh = e >> 6, d = e & 63;
                    int b = m >> 11, s = m & 2047;
                    int bh = b * Hh + hh;
                    if (part == 0) {
                        size_t i0 = ((size_t)bh * Sq + s) * Dd + d;
                        *(__half2*)(Qh + i0) =
                            __half2(__float2half(v0 * 0.125f), __float2half(v1 * 0.125f));
                    } else if (part == 1) {
                        size_t i0 = ((size_t)bh * Sq + s) * Dd + d;
                        *(__half2*)(Kh + i0) =
                            __half2(__float2half(v0), __float2half(v1));
                    } else {
                        size_t i0 = ((size_t)bh * Dd + d) * Sq + s;
                        Vth[i0]      = __float2half(v0);
                        Vth[i0 + Sq] = __float2half(v1);
                    }
                }
            }
        }
    }
}

// ---------------------------------------------------------------------------
// Flash attention, single fp16: QK = Q*K^T, PV = P*V.
// CTA: 128 q rows, 8 warps (16 q rows each). Key tiles of 64, cp.async 2-stage.
// smem: Q [128][72]; per stage K,Vt [64][72].
// ---------------------------------------------------------------------------
#define AST0  18432
#define ASTG  18432
#define ASMEM (AST0 + 2*ASTG)   // 55296

__global__ __launch_bounds__(256, 2)
void attn_mma(const __half* __restrict__ Qg, const __half* __restrict__ Khg,
              const __half* __restrict__ Vhg, __half* __restrict__ Oh)
{
    extern __shared__ __align__(16) char sma[];
    uint32_t sb = smem_u32(sma);
    int tid = threadIdx.x, lane = tid & 31, w = tid >> 5;
    int g = lane >> 2, t2 = (lane & 3) * 2;
    int bh = blockIdx.y;
    int qt = gridDim.x - 1 - (int)blockIdx.x;   // heavy q-tiles first
    int q0 = qt * 128;

    uint32_t qOff = (uint32_t)((w * 16 + (lane & 15)) * 144 + ((lane >> 4) << 3) * 2);
    uint32_t kOff = (uint32_t)((((lane >> 4) << 3) + (lane & 7)) * 144 +
                               (((lane >> 3) & 1) << 3) * 2);

    const __half* Khb = Khg + (size_t)bh * Sq * Dd;
    const __half* Vhb = Vhg + (size_t)bh * Dd * Sq;

    // Q tile -> smem
    {
        const __half* qp = Qg + ((size_t)bh * Sq + q0) * Dd;
        #pragma unroll
        for (int it = 0; it < 4; it++) {
            int idx = tid + it * 256;           // 0..1023
            int r = idx >> 3, cg = idx & 7;     // 128 rows x 8 chunks
            CPA(sb + r * 144 + cg * 16, qp + (size_t)r * Dd + cg * 8);
        }
        CP_COMMIT();
    }

    auto load_tile = [&](int t, int st) {
        uint32_t stb = sb + AST0 + st * ASTG;
        int k0 = t * 64;
        #pragma unroll
        for (int it = 0; it < 2; it++) {
            int idx = tid + it * 256;           // 0..511
            int r = idx >> 3, cg = idx & 7;     // 64 rows x 8 chunks
            CPA(stb +        r * 144 + cg * 16, Khb + (size_t)(k0 + r) * Dd + cg * 8);
            CPA(stb + 9216 + r * 144 + cg * 16, Vhb + (size_t)r * Sq + k0 + cg * 8);
        }
        CP_COMMIT();
    };

    int T = 2 * qt + 2;
    load_tile(0, 0);

    float o[8][4] = {};
    float m0r = -1e30f, m1r = -1e30f, l0 = 0.f, l1 = 0.f;
    int qwmin = q0 + w * 16;

    for (int t = 0; t < T; t++) {
        if (t + 1 < T) { load_tile(t + 1, (t + 1) & 1); CP_WAIT1(); }
        else           { CP_WAIT0(); }
        __syncthreads();

        if (64 * t <= qwmin + 15) {
            uint32_t kb = sb + AST0 + (t & 1) * ASTG;

            // ---- QK ----
            float s[8][4] = {};
            #pragma unroll
            for (int ks = 0; ks < 4; ks++) {
                int kk = ks * 16;
                uint32_t aF[4];
                LDSM4(aF, sb + qOff + kk * 2);
                #pragma unroll
                for (int jp = 0; jp < 2; jp++) {
                    int j2a = 2 * jp, j2b = 2 * jp + 1;
                    uint32_t b0[4], b1[4];
                    LDSM4(b0, kb + kOff + j2a * 2304 + kk * 2);
                    LDSM4(b1, kb + kOff + j2b * 2304 + kk * 2);
                    mma_f16(s[2*j2a],   aF, b0[0], b0[1]);
                    mma_f16(s[2*j2a+1], aF, b0[2], b0[3]);
                    mma_f16(s[2*j2b],   aF, b1[0], b1[1]);
                    mma_f16(s[2*j2b+1], aF, b1[2], b1[3]);
                }
            }

            // ---- causal mask ----
            if (64 * t + 63 > qwmin) {
                int qr0 = qwmin + g, qr1 = qwmin + g + 8;
                #pragma unroll
                for (int j = 0; j < 8; j++) {
                    int kbi = 64 * t + j * 8 + t2;
                    if (kbi     > qr0) s[j][0] = -1e30f;
                    if (kbi + 1 > qr0) s[j][1] = -1e30f;
                    if (kbi     > qr1) s[j][2] = -1e30f;
                    if (kbi + 1 > qr1) s[j][3] = -1e30f;
                }
            }

            // ---- online softmax ----
            float mx0 = -1e30f, mx1 = -1e30f;
            #pragma unroll
            for (int j = 0; j < 8; j++) {
                mx0 = fmaxf(mx0, fmaxf(s[j][0], s[j][1]));
                mx1 = fmaxf(mx1, fmaxf(s[j][2], s[j][3]));
            }
            #pragma unroll
            for (int off = 1; off < 4; off <<= 1) {
                mx0 = fmaxf(mx0, __shfl_xor_sync(0xffffffffu, mx0, off, 4));
                mx1 = fmaxf(mx1, __shfl_xor_sync(0xffffffffu, mx1, off, 4));
            }
            mx0 = fmaxf(mx0, m0r);
            mx1 = fmaxf(mx1, m1r);
            float al0 = __expf(m0r - mx0), al1 = __expf(m1r - mx1);
            m0r = mx0; m1r = mx1;
            l0 *= al0;  l1 *= al1;
            #pragma unroll
            for (int j = 0; j < 8; j++) {
                s[j][0] = __expf(s[j][0] - mx0);
                s[j][1] = __expf(s[j][1] - mx0);
                s[j][2] = __expf(s[j][2] - mx1);
                s[j][3] = __expf(s[j][3] - mx1);
                l0 += s[j][0] + s[j][1];
                l1 += s[j][2] + s[j][3];
                o[j][0] *= al0; o[j][1] *= al0;
                o[j][2] *= al1; o[j][3] *= al1;
            }

            // ---- PV (P single fp16) ----
            #pragma unroll
            for (int ks = 0; ks < 4; ks++) {
                int j0 = 2 * ks, j1 = 2 * ks + 1;
                uint32_t pF[4];
                pF[0] = pack2(__float2half(s[j0][0]), __float2half(s[j0][1]));
                pF[1] = pack2(__float2half(s[j0][2]), __float2half(s[j0][3]));
                pF[2] = pack2(__float2half(s[j1][0]), __float2half(s[j1][1]));
                pF[3] = pack2(__float2half(s[j1][2]), __float2half(s[j1][3]));
                #pragma unroll
                for (int jp = 0; jp < 2; jp++) {
                    int j2a = 2 * jp, j2b = 2 * jp + 1;
                    uint32_t v0[4], v1[4];
                    LDSM4(v0, kb + 9216 + kOff + j2a * 2304 + ks * 32);
                    LDSM4(v1, kb + 9216 + kOff + j2b * 2304 + ks * 32);
                    mma_f16(o[2*j2a],   pF, v0[0], v0[1]);
                    mma_f16(o[2*j2a+1], pF, v0[2], v0[3]);
                    mma_f16(o[2*j2b],   pF, v1[0], v1[1]);
                    mma_f16(o[2*j2b+1], pF, v1[2], v1[3]);
                }
            }
        }
        __syncthreads();
    }

    // ---- finalize ----
    #pragma unroll
    for (int off = 1; off < 4; off <<= 1) {
        l0 += __shfl_xor_sync(0xffffffffu, l0, off, 4);
        l1 += __shfl_xor_sync(0xffffffffu, l1, off, 4);
    }
    float inv0 = 1.f / l0, inv1 = 1.f / l1;
    int b = bh >> 4, hh = bh & 15;
    int r0 = q0 + w * 16 + g, r1 = r0 + 8;
    #pragma unroll
    for (int j = 0; j < 8; j++) {
        int d = j * 8 + t2;
        size_t i0 = ((size_t)(b * Sq + r0)) * Ee + hh * Dd + d;
        *(__half2*)(Oh + i0) =
            __half2(__float2half(o[j][0] * inv0), __float2half(o[j][1] * inv0));
        size_t i1 = ((size_t)(b * Sq + r1)) * Ee + hh * Dd + d;
        *(__half2*)(Oh + i1) =
            __half2(__float2half(o[j][2] * inv1), __float2half(o[j][3] * inv1));
    }
}

// ---------------------------------------------------------------------------
extern "C" void kernel_launch(void* const* d_in, const int* in_sizes, int n_in,
                              void* d_out, int out_size)
{
    const float* x      = (const float*)d_in[0];
    const float* W_attn = (const float*)d_in[1];
    const float* b_attn = (const float*)d_in[2];
    const float* W_proj = (const float*)d_in[3];
    const float* b_proj = (const float*)d_in[4];
    float* out = (float*)d_out;

    __half *xh, *wah, *wph, *qh, *kh, *vth, *oh;
    cudaGetSymbolAddress((void**)&xh, g_xh);
    cudaGetSymbolAddress((void**)&wah, g_wah);
    cudaGetSymbolAddress((void**)&wph, g_wph);
    cudaGetSymbolAddress((void**)&qh, g_qh);
    cudaGetSymbolAddress((void**)&kh, g_kh);
    cudaGetSymbolAddress((void**)&vth, g_vth);
    cudaGetSymbolAddress((void**)&oh, g_oh);

    cudaFuncSetAttribute(gemm_mma<0>, cudaFuncAttributeMaxDynamicSharedMemorySize, GSMEM);
    cudaFuncSetAttribute(gemm_mma<1>, cudaFuncAttributeMaxDynamicSharedMemorySize, GSMEM);
    cudaFuncSetAttribute(attn_mma,    cudaFuncAttributeMaxDynamicSharedMemorySize, ASMEM);

    // 0) fp32 -> fp16 conversions
    conv_single<<<Mrows*Ee/1024, 256>>>(x, xh, Mrows*Ee);
    conv_single<<<3*Ee*Ee/1024, 256>>>(W_attn, wah, 3*Ee*Ee);
    conv_single<<<Ee*Ee/1024, 256>>>(W_proj, wph, Ee*Ee);

    // 1) QKV projection -> q (scaled), k, V^T   (all fp16)
    gemm_mma<1><<<dim3(3*Ee/128, Mrows/128), 256, GSMEM>>>(
        xh, wah, b_attn, nullptr, qh, kh, vth, Mrows, 3*Ee, Ee);

    // 2) Causal flash attention -> merged-head fp16
    attn_mma<<<dim3(Sq/128, Bb*Hh), 256, ASMEM>>>(qh, kh, vth, oh);

    // 3) Output projection -> fp32 out
    gemm_mma<0><<<dim3(Ee/128, Mrows/128), 256, GSMEM>>>(
        oh, wph, b_proj, out, nullptr, nullptr, nullptr, Mrows, Ee, Ee);
}

// round 9
// speedup vs baseline: 8.3948x; 1.1575x over previous
#include <cuda_runtime.h>
#include <cuda_fp16.h>
#include <cstdint>

// Problem constants
#define Bb 2
#define Sq 2048
#define Ee 1024
#define Hh 16
#define Dd 64
#define Mrows (Bb*Sq)   // 4096

// Scratch (device globals: allocation-free, graph-capturable)
__device__ __half g_xh[(size_t)Mrows*Ee];                  // x fp16
__device__ __half g_wah[(size_t)3*Ee*Ee];                  // W_attn fp16
__device__ __half g_wph[(size_t)Ee*Ee];                    // W_proj fp16
__device__ __half g_qh[(size_t)Bb*Hh*Sq*Dd];               // q fp16 (pre-scaled by 0.125*log2e)
__device__ __half g_kh[(size_t)Bb*Hh*Sq*Dd];               // k fp16
__device__ __half g_vth[(size_t)Bb*Hh*Dd*Sq];              // V^T fp16 [bh][d][s]
__device__ __half g_oh[(size_t)Mrows*Ee];                  // attn out fp16

// ---------------------------------------------------------------------------
// helpers (all plain sm_80-era PTX: valid on compute_103 virtual arch)
// ---------------------------------------------------------------------------
__device__ __forceinline__ uint32_t smem_u32(const void* p) {
    uint32_t a;
    asm("{ .reg .u64 t; cvta.to.shared.u64 t, %1; cvt.u32.u64 %0, t; }"
        : "=r"(a) : "l"(p));
    return a;
}
#define CPA(dst, src) \
    asm volatile("cp.async.cg.shared.global [%0], [%1], 16;" :: "r"(dst), "l"(src))
#define CP_COMMIT() asm volatile("cp.async.commit_group;")
#define CP_WAIT1()  asm volatile("cp.async.wait_group 1;" ::: "memory")
#define CP_WAIT0()  asm volatile("cp.async.wait_group 0;" ::: "memory")

#define LDSM4(r, addr) \
    asm volatile("ldmatrix.sync.aligned.m8n8.x4.shared.b16 {%0,%1,%2,%3}, [%4];" \
        : "=r"((r)[0]), "=r"((r)[1]), "=r"((r)[2]), "=r"((r)[3]) : "r"(addr))

__device__ __forceinline__ void mma_f16(float* c, const uint32_t* a,
                                        uint32_t b0, uint32_t b1) {
    asm volatile(
        "mma.sync.aligned.m16n8k16.row.col.f32.f16.f16.f32 "
        "{%0,%1,%2,%3}, {%4,%5,%6,%7}, {%8,%9}, {%0,%1,%2,%3};"
        : "+f"(c[0]), "+f"(c[1]), "+f"(c[2]), "+f"(c[3])
        : "r"(a[0]), "r"(a[1]), "r"(a[2]), "r"(a[3]), "r"(b0), "r"(b1));
}

__device__ __forceinline__ uint32_t pack2(__half lo, __half hi) {
    __half2 t(lo, hi);
    return *(uint32_t*)&t;
}

// ---------------------------------------------------------------------------
// fused fp32 -> fp16 conversion for x, W_attn, W_proj (one launch)
// ---------------------------------------------------------------------------
#define NX (Mrows*Ee)          // 4194304
#define NWA (3*Ee*Ee)          // 3145728
#define NWP (Ee*Ee)            // 1048576

__global__ __launch_bounds__(256)
void conv_all(const float* __restrict__ x, const float* __restrict__ wa,
              const float* __restrict__ wp, __half* __restrict__ xh,
              __half* __restrict__ wah, __half* __restrict__ wph)
{
    int i = (blockIdx.x * 256 + threadIdx.x) * 4;
    const float* src; __half* dst; int off;
    if (i < NX)            { src = x;  dst = xh;  off = 0; }
    else if (i < NX + NWA) { src = wa; dst = wah; off = NX; }
    else                   { src = wp; dst = wph; off = NX + NWA; }
    int j = i - off;
    float4 v = *(const float4*)(src + j);
    ((__half2*)(dst + j))[0] = __half2(__float2half(v.x), __float2half(v.y));
    ((__half2*)(dst + j))[1] = __half2(__float2half(v.z), __float2half(v.w));
}

// ---------------------------------------------------------------------------
// GEMM: C[M,N] = A_f16[M,K] @ B_f16[N,K]^T + bias  (single fp16 product)
// 128x128 CTA tile, 8 warps (warp tile 32x64), K-chunk 64, cp.async 2-stage,
// ldmatrix.x4, 2 CTAs/SM. smem stage: A,B each [128][72] half -> 36864B.
// ---------------------------------------------------------------------------
#define GST   36864
#define GSMEM (2*GST)

template<int SCATTER>
__global__ __launch_bounds__(256, 2)
void gemm_mma(const __half* __restrict__ Ag, const __half* __restrict__ Bg,
              const float* __restrict__ bias, float* __restrict__ C,
              __half* __restrict__ Qh, __half* __restrict__ Kh,
              __half* __restrict__ Vth,
              int M, int N, int K)
{
    extern __shared__ __align__(16) char smg[];
    uint32_t sb = smem_u32(smg);
    int tid = threadIdx.x;
    int lane = tid & 31, warp = tid >> 5;
    int wm = warp >> 1, wn = warp & 1;
    int g = lane >> 2, t2 = (lane & 3) * 2;
    int m0 = blockIdx.y * 128, n0 = blockIdx.x * 128;

    uint32_t aOff = (uint32_t)((wm * 32 + (lane & 15)) * 144 + ((lane >> 4) << 3) * 2);
    uint32_t bOff = (uint32_t)((wn * 64 + ((lane >> 4) << 3) + (lane & 7)) * 144 +
                               (((lane >> 3) & 1) << 3) * 2);

    const __half* srcs[2] = { Ag + (size_t)m0 * K, Bg + (size_t)n0 * K };

    auto load_chunk = [&](int kt, int st) {
        uint32_t stb = sb + st * GST;
        #pragma unroll
        for (int b = 0; b < 2; b++) {
            const __half* base = srcs[b] + kt;
            #pragma unroll
            for (int it = 0; it < 4; it++) {
                int idx = tid + it * 256;            // 0..1023
                int r = idx >> 3, cg = idx & 7;      // 128 rows x 8 chunks(16B)
                CPA(stb + b * 18432 + r * 144 + cg * 16,
                    base + (size_t)r * K + cg * 8);
            }
        }
        CP_COMMIT();
    };

    float acc[2][8][4] = {};
    load_chunk(0, 0);
    int nch = K >> 6;
    for (int c = 0; c < nch; c++) {
        if (c + 1 < nch) { load_chunk((c + 1) * 64, (c + 1) & 1); CP_WAIT1(); }
        else             { CP_WAIT0(); }
        __syncthreads();
        uint32_t stb = sb + (c & 1) * GST;
        #pragma unroll
        for (int kk = 0; kk < 64; kk += 16) {
            uint32_t aF[2][4];
            LDSM4(aF[0], stb + aOff + kk * 2);
            LDSM4(aF[1], stb + aOff + kk * 2 + 16 * 144);
            #pragma unroll
            for (int j2 = 0; j2 < 4; j2++) {
                uint32_t bf[4];
                LDSM4(bf, stb + 18432 + bOff + j2 * 2304 + kk * 2);
                mma_f16(acc[0][2*j2],   aF[0], bf[0], bf[1]);
                mma_f16(acc[1][2*j2],   aF[1], bf[0], bf[1]);
                mma_f16(acc[0][2*j2+1], aF[0], bf[2], bf[3]);
                mma_f16(acc[1][2*j2+1], aF[1], bf[2], bf[3]);
            }
        }
        __syncthreads();
    }

    // epilogue
    const float QSC = 0.125f * 1.44269504088896f;   // fold scale*log2(e) into q
    #pragma unroll
    for (int i = 0; i < 2; i++) {
        #pragma unroll
        for (int e2 = 0; e2 < 2; e2++) {
            int m = m0 + wm * 32 + i * 16 + g + e2 * 8;
            #pragma unroll
            for (int j = 0; j < 8; j++) {
                int n = n0 + wn * 64 + j * 8 + t2;
                float v0 = acc[i][j][e2*2+0] + bias[n];
                float v1 = acc[i][j][e2*2+1] + bias[n+1];
                if (SCATTER == 0) {
                    *(float2*)(C + (size_t)m * N + n) = make_float2(v0, v1);
                } else {
                    int part = n >> 10, e = n & 1023, hh = e >> 6, d = e & 63;
                    int b = m >> 11, s = m & 2047;
                    int bh = b * Hh + hh;
                    if (part == 0) {
                        size_t i0 = ((size_t)bh * Sq + s) * Dd + d;
                        *(__half2*)(Qh + i0) =
                            __half2(__float2half(v0 * QSC), __float2half(v1 * QSC));
                    } else if (part == 1) {
                        size_t i0 = ((size_t)bh * Sq + s) * Dd + d;
                        *(__half2*)(Kh + i0) =
                            __half2(__float2half(v0), __float2half(v1));
                    } else {
                        size_t i0 = ((size_t)bh * Dd + d) * Sq + s;
                        Vth[i0]      = __float2half(v0);
                        Vth[i0 + Sq] = __float2half(v1);
                    }
                }
            }
        }
    }
}

// ---------------------------------------------------------------------------
// Flash attention, single fp16, 128-key smem tiles (two 64-key compute passes)
// CTA: 128 q rows, 8 warps (16 q rows each). cp.async 2-stage, exp2 softmax.
// smem: Q [128][72]; per stage K [128][72] + Vt [64][136].
// ---------------------------------------------------------------------------
#define AQ    18432
#define AKST  18432
#define AVST  17408
#define ASTG  (AKST + AVST)        // 35840
#define ASMEM (AQ + 2*ASTG)        // 90112

__global__ __launch_bounds__(256, 2)
void attn_mma(const __half* __restrict__ Qg, const __half* __restrict__ Khg,
              const __half* __restrict__ Vhg, __half* __restrict__ Oh)
{
    extern __shared__ __align__(16) char sma[];
    uint32_t sb = smem_u32(sma);
    int tid = threadIdx.x, lane = tid & 31, w = tid >> 5;
    int g = lane >> 2, t2 = (lane & 3) * 2;
    int bh = blockIdx.y;
    int qt = gridDim.x - 1 - (int)blockIdx.x;   // heavy q-tiles first
    int q0 = qt * 128;

    uint32_t qOff = (uint32_t)((w * 16 + (lane & 15)) * 144 + ((lane >> 4) << 3) * 2);
    uint32_t kOff = (uint32_t)((((lane >> 4) << 3) + (lane & 7)) * 144 +
                               (((lane >> 3) & 1) << 3) * 2);
    uint32_t vOff = (uint32_t)((((lane >> 4) << 3) + (lane & 7)) * 272 +
                               (((lane >> 3) & 1) << 3) * 2);

    const __half* Khb = Khg + (size_t)bh * Sq * Dd;
    const __half* Vhb = Vhg + (size_t)bh * Dd * Sq;

    // Q tile -> smem
    {
        const __half* qp = Qg + ((size_t)bh * Sq + q0) * Dd;
        #pragma unroll
        for (int it = 0; it < 4; it++) {
            int idx = tid + it * 256;           // 0..1023
            int r = idx >> 3, cg = idx & 7;     // 128 rows x 8 chunks
            CPA(sb + r * 144 + cg * 16, qp + (size_t)r * Dd + cg * 8);
        }
        CP_COMMIT();
    }

    auto load_tile = [&](int t, int st) {
        uint32_t stb = sb + AQ + st * ASTG;
        int k0 = t * 128;
        // K: 128 key rows x 64 d
        #pragma unroll
        for (int it = 0; it < 4; it++) {
            int idx = tid + it * 256;
            int r = idx >> 3, cg = idx & 7;
            CPA(stb + r * 144 + cg * 16, Khb + (size_t)(k0 + r) * Dd + cg * 8);
        }
        // Vt: 64 d rows x 128 keys
        #pragma unroll
        for (int it = 0; it < 4; it++) {
            int idx = tid + it * 256;           // 0..1023
            int r = idx >> 4, cg = idx & 15;    // 64 rows x 16 chunks(16B)
            CPA(stb + AKST + r * 272 + cg * 16, Vhb + (size_t)r * Sq + k0 + cg * 8);
        }
        CP_COMMIT();
    };

    int T = qt + 1;
    load_tile(0, 0);

    float o[8][4] = {};
    float m0r = -1e30f, m1r = -1e30f, l0 = 0.f, l1 = 0.f;
    int qwmin = q0 + w * 16;

    for (int t = 0; t < T; t++) {
        if (t + 1 < T) { load_tile(t + 1, (t + 1) & 1); CP_WAIT1(); }
        else           { CP_WAIT0(); }
        __syncthreads();
        uint32_t kb = sb + AQ + (t & 1) * ASTG;

        #pragma unroll
        for (int h = 0; h < 2; h++) {
            int kbase = 128 * t + 64 * h;
            if (kbase > qwmin + 15) break;
            uint32_t kh = kb + h * 9216;          // 64 key rows into K buffer
            uint32_t vh = kb + AKST + h * 128;    // 64 key cols into Vt buffer

            // ---- QK ----
            float s[8][4] = {};
            #pragma unroll
            for (int ks = 0; ks < 4; ks++) {
                int kk = ks * 16;
                uint32_t aF[4];
                LDSM4(aF, sb + qOff + kk * 2);
                #pragma unroll
                for (int jp = 0; jp < 2; jp++) {
                    int j2a = 2 * jp, j2b = 2 * jp + 1;
                    uint32_t b0[4], b1[4];
                    LDSM4(b0, kh + kOff + j2a * 2304 + kk * 2);
                    LDSM4(b1, kh + kOff + j2b * 2304 + kk * 2);
                    mma_f16(s[2*j2a],   aF, b0[0], b0[1]);
                    mma_f16(s[2*j2a+1], aF, b0[2], b0[3]);
                    mma_f16(s[2*j2b],   aF, b1[0], b1[1]);
                    mma_f16(s[2*j2b+1], aF, b1[2], b1[3]);
                }
            }

            // ---- causal mask ----
            if (kbase + 63 > qwmin) {
                int qr0 = qwmin + g, qr1 = qwmin + g + 8;
                #pragma unroll
                for (int j = 0; j < 8; j++) {
                    int kbi = kbase + j * 8 + t2;
                    if (kbi     > qr0) s[j][0] = -1e30f;
                    if (kbi + 1 > qr0) s[j][1] = -1e30f;
                    if (kbi     > qr1) s[j][2] = -1e30f;
                    if (kbi + 1 > qr1) s[j][3] = -1e30f;
                }
            }

            // ---- online softmax (base-2; q pre-scaled by log2e) ----
            float mx0 = -1e30f, mx1 = -1e30f;
            #pragma unroll
            for (int j = 0; j < 8; j++) {
                mx0 = fmaxf(mx0, fmaxf(s[j][0], s[j][1]));
                mx1 = fmaxf(mx1, fmaxf(s[j][2], s[j][3]));
            }
            #pragma unroll
            for (int off = 1; off < 4; off <<= 1) {
                mx0 = fmaxf(mx0, __shfl_xor_sync(0xffffffffu, mx0, off, 4));
                mx1 = fmaxf(mx1, __shfl_xor_sync(0xffffffffu, mx1, off, 4));
            }
            mx0 = fmaxf(mx0, m0r);
            mx1 = fmaxf(mx1, m1r);
            float al0 = exp2f(m0r - mx0), al1 = exp2f(m1r - mx1);
            m0r = mx0; m1r = mx1;
            l0 *= al0;  l1 *= al1;
            #pragma unroll
            for (int j = 0; j < 8; j++) {
                s[j][0] = exp2f(s[j][0] - mx0);
                s[j][1] = exp2f(s[j][1] - mx0);
                s[j][2] = exp2f(s[j][2] - mx1);
                s[j][3] = exp2f(s[j][3] - mx1);
                l0 += s[j][0] + s[j][1];
                l1 += s[j][2] + s[j][3];
                o[j][0] *= al0; o[j][1] *= al0;
                o[j][2] *= al1; o[j][3] *= al1;
            }

            // ---- PV (P single fp16) ----
            #pragma unroll
            for (int ks = 0; ks < 4; ks++) {
                int j0 = 2 * ks, j1 = 2 * ks + 1;
                uint32_t pF[4];
                pF[0] = pack2(__float2half(s[j0][0]), __float2half(s[j0][1]));
                pF[1] = pack2(__float2half(s[j0][2]), __float2half(s[j0][3]));
                pF[2] = pack2(__float2half(s[j1][0]), __float2half(s[j1][1]));
                pF[3] = pack2(__float2half(s[j1][2]), __float2half(s[j1][3]));
                #pragma unroll
                for (int jp = 0; jp < 2; jp++) {
                    int j2a = 2 * jp, j2b = 2 * jp + 1;
                    uint32_t v0[4], v1[4];
                    LDSM4(v0, vh + vOff + j2a * 4352 + ks * 32);
                    LDSM4(v1, vh + vOff + j2b * 4352 + ks * 32);
                    mma_f16(o[2*j2a],   pF, v0[0], v0[1]);
                    mma_f16(o[2*j2a+1], pF, v0[2], v0[3]);
                    mma_f16(o[2*j2b],   pF, v1[0], v1[1]);
                    mma_f16(o[2*j2b+1], pF, v1[2], v1[3]);
                }
            }
        }
        __syncthreads();
    }

    // ---- finalize ----
    #pragma unroll
    for (int off = 1; off < 4; off <<= 1) {
        l0 += __shfl_xor_sync(0xffffffffu, l0, off, 4);
        l1 += __shfl_xor_sync(0xffffffffu, l1, off, 4);
    }
    float inv0 = 1.f / l0, inv1 = 1.f / l1;
    int b = bh >> 4, hh = bh & 15;
    int r0 = q0 + w * 16 + g, r1 = r0 + 8;
    #pragma unroll
    for (int j = 0; j < 8; j++) {
        int d = j * 8 + t2;
        size_t i0 = ((size_t)(b * Sq + r0)) * Ee + hh * Dd + d;
        *(__half2*)(Oh + i0) =
            __half2(__float2half(o[j][0] * inv0), __float2half(o[j][1] * inv0));
        size_t i1 = ((size_t)(b * Sq + r1)) * Ee + hh * Dd + d;
        *(__half2*)(Oh + i1) =
            __half2(__float2half(o[j][2] * inv1), __float2half(o[j][3] * inv1));
    }
}

// ---------------------------------------------------------------------------
extern "C" void kernel_launch(void* const* d_in, const int* in_sizes, int n_in,
                              void* d_out, int out_size)
{
    const float* x      = (const float*)d_in[0];
    const float* W_attn = (const float*)d_in[1];
    const float* b_attn = (const float*)d_in[2];
    const float* W_proj = (const float*)d_in[3];
    const float* b_proj = (const float*)d_in[4];
    float* out = (float*)d_out;

    __half *xh, *wah, *wph, *qh, *kh, *vth, *oh;
    cudaGetSymbolAddress((void**)&xh, g_xh);
    cudaGetSymbolAddress((void**)&wah, g_wah);
    cudaGetSymbolAddress((void**)&wph, g_wph);
    cudaGetSymbolAddress((void**)&qh, g_qh);
    cudaGetSymbolAddress((void**)&kh, g_kh);
    cudaGetSymbolAddress((void**)&vth, g_vth);
    cudaGetSymbolAddress((void**)&oh, g_oh);

    cudaFuncSetAttribute(gemm_mma<0>, cudaFuncAttributeMaxDynamicSharedMemorySize, GSMEM);
    cudaFuncSetAttribute(gemm_mma<1>, cudaFuncAttributeMaxDynamicSharedMemorySize, GSMEM);
    cudaFuncSetAttribute(attn_mma,    cudaFuncAttributeMaxDynamicSharedMemorySize, ASMEM);

    // 0) fp32 -> fp16 conversions (single fused launch)
    conv_all<<<(NX + NWA + NWP) / 1024, 256>>>(x, W_attn, W_proj, xh, wah, wph);

    // 1) QKV projection -> q (scaled by 0.125*log2e), k, V^T   (all fp16)
    gemm_mma<1><<<dim3(3*Ee/128, Mrows/128), 256, GSMEM>>>(
        xh, wah, b_attn, nullptr, qh, kh, vth, Mrows, 3*Ee, Ee);

    // 2) Causal flash attention -> merged-head fp16
    attn_mma<<<dim3(Sq/128, Bb*Hh), 256, ASMEM>>>(qh, kh, vth, oh);

    // 3) Output projection -> fp32 out
    gemm_mma<0><<<dim3(Ee/128, Mrows/128), 256, GSMEM>>>(
        oh, wph, b_proj, out, nullptr, nullptr, nullptr, Mrows, Ee, Ee);
}